// round 1
// baseline (speedup 1.0000x reference)
#include <cuda_runtime.h>
#include <math.h>

// Problem constants
namespace {
constexpr int B_   = 32;
constexpr int N_   = 512;
constexpr int C_   = 768;
constexpr int H_   = 12;
constexpr int D_   = 64;
constexpr int HID_ = 3072;
constexpr int M_   = B_ * N_;   // 16384 tokens
constexpr int BH_  = B_ * H_;   // 384 attention batches
}

// Scratch (static __device__ arrays: allocation-free per harness rules)
__device__ float g_h[M_ * C_];                       // LN output (reused for LN1 and LN2)
__device__ float g_qkv[M_ * 3 * C_];                 // fused QKV output [M, 2304]
__device__ float g_S[(size_t)BH_ * N_ * N_];         // attention scores [B*H, N, N]
__device__ float g_o[M_ * C_];                       // attention output merged [M, C]
__device__ float g_xres[M_ * C_];                    // 2*(proj out + bias) residual
__device__ float g_fc1[M_ * HID_];                   // GELU(fc1) activations

// ---------------------------------------------------------------------------
// LayerNorm: one block (256 threads) per 768-wide row
// ---------------------------------------------------------------------------
__global__ void ln_kernel(const float* __restrict__ x, const float* __restrict__ w,
                          const float* __restrict__ bia, float* __restrict__ out) {
    __shared__ float red[256];
    const int row = blockIdx.x;
    const int t = threadIdx.x;
    const float* xr = x + (size_t)row * C_;
    float v[3];
    float s = 0.f, s2 = 0.f;
#pragma unroll
    for (int j = 0; j < 3; j++) {
        v[j] = xr[t + 256 * j];
        s += v[j];
        s2 += v[j] * v[j];
    }
    red[t] = s; __syncthreads();
    for (int o = 128; o > 0; o >>= 1) { if (t < o) red[t] += red[t + o]; __syncthreads(); }
    const float mean = red[0] * (1.f / C_);
    __syncthreads();
    red[t] = s2; __syncthreads();
    for (int o = 128; o > 0; o >>= 1) { if (t < o) red[t] += red[t + o]; __syncthreads(); }
    const float var = red[0] * (1.f / C_) - mean * mean;
    const float rstd = rsqrtf(var + 1e-5f);
    float* orow = out + (size_t)row * C_;
#pragma unroll
    for (int j = 0; j < 3; j++) {
        const int c = t + 256 * j;
        orow[c] = (v[j] - mean) * rstd * w[c] + bia[c];
    }
}

// ---------------------------------------------------------------------------
// Softmax over rows of 512 (in place). One block (128 threads) per row.
// ---------------------------------------------------------------------------
__global__ void softmax_kernel(float* __restrict__ S) {
    __shared__ float red[128];
    const size_t row = blockIdx.x;
    float* r = S + row * N_;
    const int t = threadIdx.x;
    float v[4];
    float m = -1e30f;
#pragma unroll
    for (int j = 0; j < 4; j++) { v[j] = r[t + 128 * j]; m = fmaxf(m, v[j]); }
    red[t] = m; __syncthreads();
    for (int o = 64; o > 0; o >>= 1) { if (t < o) red[t] = fmaxf(red[t], red[t + o]); __syncthreads(); }
    m = red[0]; __syncthreads();
    float s = 0.f;
#pragma unroll
    for (int j = 0; j < 4; j++) { v[j] = __expf(v[j] - m); s += v[j]; }
    red[t] = s; __syncthreads();
    for (int o = 64; o > 0; o >>= 1) { if (t < o) red[t] += red[t + o]; __syncthreads(); }
    const float inv = 1.f / red[0];
#pragma unroll
    for (int j = 0; j < 4; j++) r[t + 128 * j] = v[j] * inv;
}

// ---------------------------------------------------------------------------
// Generic fp32 GEMM, 64x64 tile, BK=16, 256 threads, 4x4 register micro-tile.
//   C[M, Ncol] = A[M, K] * op(B)          op(B) = B[Ncol,K]^T (TRANSB) or B[K,Ncol]
// EPI: 0 = store; 1 = *0.125; 2 = 2*(acc+bias); 3 = gelu(acc+bias);
//      4 = acc+bias+res
// BMODE: 0 = single batch; 1 = QK^T per (b,h); 2 = P*V per (b,h)
// All dims here are multiples of the tile sizes (verified for every call site),
// so no bounds checks.
// ---------------------------------------------------------------------------
template <bool TRANSB, int EPI, int BMODE>
__global__ void __launch_bounds__(256) gemm_kernel(
    const float* __restrict__ A, const float* __restrict__ Bm,
    const float* __restrict__ bias, const float* __restrict__ res,
    float* __restrict__ C,
    int M, int Ncol, int K, int lda, int ldb, int ldc)
{
    constexpr int BM = 64, BN = 64, BK = 16;
    __shared__ float As[BK][BM];
    __shared__ float Bs[BK][BN];

    size_t offA = 0, offB = 0, offC = 0;
    if (BMODE == 1) {
        const int z = blockIdx.z, b = z / H_, hh = z % H_;
        offA = (size_t)b * N_ * (3 * C_) + (size_t)hh * D_;   // Q rows (d contiguous)
        offB = offA;                                          // K rows (+C_ folded into base ptr)
        offC = (size_t)z * N_ * N_;
    } else if (BMODE == 2) {
        const int z = blockIdx.z, b = z / H_, hh = z % H_;
        offA = (size_t)z * N_ * N_;                           // P rows
        offB = (size_t)b * N_ * (3 * C_) + (size_t)hh * D_;   // V rows (+2C_ folded into base)
        offC = (size_t)b * N_ * C_ + (size_t)hh * D_;         // merged o output
    }
    const float* Ab = A + offA;
    const float* Bb = Bm + offB;
    float* Cb = C + offC;

    const int row0 = blockIdx.y * BM, col0 = blockIdx.x * BN;
    const int tid = threadIdx.x;
    const int ty = tid >> 4, tx = tid & 15;

    const int lRow = tid >> 2;          // 0..63 (A / trans-B load row)
    const int lK4  = (tid & 3) * 4;     // 0,4,8,12
    const int bK   = tid >> 4;          // 0..15 (notrans-B load k)
    const int bN4  = (tid & 15) * 4;

    float acc[4][4] = {};

    for (int k0 = 0; k0 < K; k0 += BK) {
        const float4 av = *(const float4*)(Ab + (size_t)(row0 + lRow) * lda + k0 + lK4);
        As[lK4 + 0][lRow] = av.x;
        As[lK4 + 1][lRow] = av.y;
        As[lK4 + 2][lRow] = av.z;
        As[lK4 + 3][lRow] = av.w;
        if (TRANSB) {
            const float4 bv = *(const float4*)(Bb + (size_t)(col0 + lRow) * ldb + k0 + lK4);
            Bs[lK4 + 0][lRow] = bv.x;
            Bs[lK4 + 1][lRow] = bv.y;
            Bs[lK4 + 2][lRow] = bv.z;
            Bs[lK4 + 3][lRow] = bv.w;
        } else {
            const float4 bv = *(const float4*)(Bb + (size_t)(k0 + bK) * ldb + col0 + bN4);
            *(float4*)&Bs[bK][bN4] = bv;
        }
        __syncthreads();
#pragma unroll
        for (int k = 0; k < BK; k++) {
            const float4 a4 = *(const float4*)&As[k][ty * 4];
            const float4 b4 = *(const float4*)&Bs[k][tx * 4];
            const float ar[4] = {a4.x, a4.y, a4.z, a4.w};
            const float br[4] = {b4.x, b4.y, b4.z, b4.w};
#pragma unroll
            for (int i = 0; i < 4; i++)
#pragma unroll
                for (int j = 0; j < 4; j++)
                    acc[i][j] += ar[i] * br[j];
        }
        __syncthreads();
    }

#pragma unroll
    for (int i = 0; i < 4; i++) {
        const int r = row0 + ty * 4 + i;
#pragma unroll
        for (int j = 0; j < 4; j++) {
            const int c = col0 + tx * 4 + j;
            float v = acc[i][j];
            if (EPI == 1) v *= 0.125f;                        // 1/sqrt(D)
            if (EPI == 2 || EPI == 3 || EPI == 4) v += bias[c];
            if (EPI == 2) v *= 2.f;                           // x = o + o quirk
            if (EPI == 3) v = 0.5f * v * (1.f + erff(v * 0.70710678118654752f)); // exact GELU
            if (EPI == 4) v += res[(size_t)r * ldc + c];      // final residual
            Cb[(size_t)r * ldc + c] = v;
        }
    }
}

// ---------------------------------------------------------------------------
// Launch sequence (graph-capturable: kernel launches only)
// ---------------------------------------------------------------------------
extern "C" void kernel_launch(void* const* d_in, const int* in_sizes, int n_in,
                              void* d_out, int out_size) {
    (void)in_sizes; (void)n_in; (void)out_size;
    const float* x      = (const float*)d_in[0];
    const float* ln1_w  = (const float*)d_in[1];
    const float* ln1_b  = (const float*)d_in[2];
    const float* qkv_w  = (const float*)d_in[3];
    const float* proj_w = (const float*)d_in[4];
    const float* proj_b = (const float*)d_in[5];
    const float* ln2_w  = (const float*)d_in[6];
    const float* ln2_b  = (const float*)d_in[7];
    const float* fc1_w  = (const float*)d_in[8];
    const float* fc1_b  = (const float*)d_in[9];
    const float* fc2_w  = (const float*)d_in[10];
    const float* fc2_b  = (const float*)d_in[11];
    float* out = (float*)d_out;

    float *h, *qkv, *S, *o, *xres, *fc1;
    cudaGetSymbolAddress((void**)&h,    g_h);
    cudaGetSymbolAddress((void**)&qkv,  g_qkv);
    cudaGetSymbolAddress((void**)&S,    g_S);
    cudaGetSymbolAddress((void**)&o,    g_o);
    cudaGetSymbolAddress((void**)&xres, g_xres);
    cudaGetSymbolAddress((void**)&fc1,  g_fc1);

    // 1. LN1: h = layer_norm(x)
    ln_kernel<<<M_, 256>>>(x, ln1_w, ln1_b, h);

    // 2. QKV: qkv = h @ qkv_w^T       [16384, 2304]
    gemm_kernel<true, 0, 0><<<dim3(3 * C_ / 64, M_ / 64, 1), 256>>>(
        h, qkv_w, nullptr, nullptr, qkv, M_, 3 * C_, C_, C_, C_, 3 * C_);

    // 3. Scores: S = (Q @ K^T) / 8, per (b,h)   [384, 512, 512]
    gemm_kernel<true, 1, 1><<<dim3(N_ / 64, N_ / 64, BH_), 256>>>(
        qkv, qkv + C_, nullptr, nullptr, S, N_, N_, D_, 3 * C_, 3 * C_, N_);

    // 4. Softmax rows of S
    softmax_kernel<<<BH_ * N_, 128>>>(S);

    // 5. O = P @ V, scatter per head into merged [16384, 768]
    gemm_kernel<false, 0, 2><<<dim3(D_ / 64, N_ / 64, BH_), 256>>>(
        S, qkv + 2 * C_, nullptr, nullptr, o, N_, D_, N_, N_, 3 * C_, C_);

    // 6. Projection + quirk: xres = 2*(o @ proj_w^T + proj_b)
    gemm_kernel<true, 2, 0><<<dim3(C_ / 64, M_ / 64, 1), 256>>>(
        o, proj_w, proj_b, nullptr, xres, M_, C_, C_, C_, C_, C_);

    // 7. LN2: h = layer_norm(xres)
    ln_kernel<<<M_, 256>>>(xres, ln2_w, ln2_b, h);

    // 8. fc1 + exact GELU: fc1_act = gelu(h @ fc1_w^T + fc1_b)   [16384, 3072]
    gemm_kernel<true, 3, 0><<<dim3(HID_ / 64, M_ / 64, 1), 256>>>(
        h, fc1_w, fc1_b, nullptr, fc1, M_, HID_, C_, C_, C_, HID_);

    // 9. fc2 + bias + residual: out = xres + fc1_act @ fc2_w^T + fc2_b
    gemm_kernel<true, 4, 0><<<dim3(C_ / 64, M_ / 64, 1), 256>>>(
        fc1, fc2_w, fc2_b, xres, out, M_, C_, HID_, HID_, HID_, C_);
}

// round 3
// speedup vs baseline: 2.2629x; 2.2629x over previous
#include <cuda_runtime.h>
#include <cuda_bf16.h>
#include <math.h>
#include <stdint.h>

namespace {
constexpr int B_   = 32;
constexpr int N_   = 512;
constexpr int C_   = 768;
constexpr int H_   = 12;
constexpr int D_   = 64;
constexpr int HID_ = 3072;
constexpr int M_   = B_ * N_;   // 16384
constexpr int BH_  = B_ * H_;   // 384
}

// Scratch
__device__ float g_h[M_ * C_];
__device__ float g_qkv[M_ * 3 * C_];
__device__ float g_S[(size_t)BH_ * N_ * N_];
__device__ float g_o[M_ * C_];
__device__ float g_xres[M_ * C_];
__device__ float g_fc1[M_ * HID_];

// ---------------------------------------------------------------------------
// helpers
// ---------------------------------------------------------------------------
__device__ __forceinline__ uint32_t smem_u32(const void* p) {
    uint32_t a;
    asm("{ .reg .u64 t; cvta.to.shared.u64 t, %1; cvt.u32.u64 %0, t; }" : "=r"(a) : "l"(p));
    return a;
}
__device__ __forceinline__ uint32_t pack_bf16(float x, float y) {
    __nv_bfloat162 t = __floats2bfloat162_rn(x, y);
    return *reinterpret_cast<uint32_t*>(&t);
}
#define LDSM_X4(r0, r1, r2, r3, addr)                                             \
    asm volatile("ldmatrix.sync.aligned.m8n8.x4.shared.b16 {%0,%1,%2,%3}, [%4];"  \
                 : "=r"(r0), "=r"(r1), "=r"(r2), "=r"(r3) : "r"(addr))
#define LDSM_X4_T(r0, r1, r2, r3, addr)                                                \
    asm volatile("ldmatrix.sync.aligned.m8n8.x4.trans.shared.b16 {%0,%1,%2,%3}, [%4];" \
                 : "=r"(r0), "=r"(r1), "=r"(r2), "=r"(r3) : "r"(addr))
__device__ __forceinline__ void mma_bf16(float* c, const uint32_t* a, const uint32_t* b) {
    asm volatile(
        "mma.sync.aligned.m16n8k16.row.col.f32.bf16.bf16.f32 "
        "{%0,%1,%2,%3}, {%4,%5,%6,%7}, {%8,%9}, {%0,%1,%2,%3};"
        : "+f"(c[0]), "+f"(c[1]), "+f"(c[2]), "+f"(c[3])
        : "r"(a[0]), "r"(a[1]), "r"(a[2]), "r"(a[3]), "r"(b[0]), "r"(b[1]));
}

__device__ __forceinline__ float apply_epi(float v, int epi, float bias_v) {
    if (epi == 1) v *= 0.125f;
    if (epi == 2) v = 2.f * (v + bias_v);
    if (epi == 3) {
        v += bias_v;
        v = 0.5f * v * (1.f + erff(v * 0.70710678118654752f));
    }
    if (epi == 4) v += bias_v;
    return v;
}

// ---------------------------------------------------------------------------
// LayerNorm
// ---------------------------------------------------------------------------
__global__ void ln_kernel(const float* __restrict__ x, const float* __restrict__ w,
                          const float* __restrict__ bia, float* __restrict__ out) {
    __shared__ float red[256];
    const int row = blockIdx.x;
    const int t = threadIdx.x;
    const float* xr = x + (size_t)row * C_;
    float v[3];
    float s = 0.f, s2 = 0.f;
#pragma unroll
    for (int j = 0; j < 3; j++) { v[j] = xr[t + 256 * j]; s += v[j]; s2 += v[j] * v[j]; }
    red[t] = s; __syncthreads();
    for (int o = 128; o > 0; o >>= 1) { if (t < o) red[t] += red[t + o]; __syncthreads(); }
    const float mean = red[0] * (1.f / C_);
    __syncthreads();
    red[t] = s2; __syncthreads();
    for (int o = 128; o > 0; o >>= 1) { if (t < o) red[t] += red[t + o]; __syncthreads(); }
    const float var = red[0] * (1.f / C_) - mean * mean;
    const float rstd = rsqrtf(var + 1e-5f);
    float* orow = out + (size_t)row * C_;
#pragma unroll
    for (int j = 0; j < 3; j++) {
        const int c = t + 256 * j;
        orow[c] = (v[j] - mean) * rstd * w[c] + bia[c];
    }
}

// ---------------------------------------------------------------------------
// Softmax
// ---------------------------------------------------------------------------
__global__ void softmax_kernel(float* __restrict__ S) {
    __shared__ float red[128];
    const size_t row = blockIdx.x;
    float* r = S + row * N_;
    const int t = threadIdx.x;
    float v[4];
    float m = -1e30f;
#pragma unroll
    for (int j = 0; j < 4; j++) { v[j] = r[t + 128 * j]; m = fmaxf(m, v[j]); }
    red[t] = m; __syncthreads();
    for (int o = 64; o > 0; o >>= 1) { if (t < o) red[t] = fmaxf(red[t], red[t + o]); __syncthreads(); }
    m = red[0]; __syncthreads();
    float s = 0.f;
#pragma unroll
    for (int j = 0; j < 4; j++) { v[j] = __expf(v[j] - m); s += v[j]; }
    red[t] = s; __syncthreads();
    for (int o = 64; o > 0; o >>= 1) { if (t < o) red[t] += red[t + o]; __syncthreads(); }
    const float inv = 1.f / red[0];
#pragma unroll
    for (int j = 0; j < 4; j++) r[t + 128 * j] = v[j] * inv;
}

// ---------------------------------------------------------------------------
// bf16-split HMMA GEMM.  C[M,N] = A[M,K] @ B[N,K]^T   (fp32 in/out)
// 128x128 tile, BK=32, 8 warps (2x4), warp tile 64x32, 3-term split.
// EPI: 0 store; 1 *0.125; 2 2*(v+bias); 3 gelu(v+bias); 4 v+bias+res
// BMODE: 0 plain; 1 = QK^T per (b,h)
// ---------------------------------------------------------------------------
template <int EPI, int BMODE>
__global__ void __launch_bounds__(256) mma_gemm(
    const float* __restrict__ A, const float* __restrict__ Bm,
    const float* __restrict__ bias, const float* __restrict__ res,
    float* __restrict__ C, int K, int lda, int ldb, int ldc)
{
    constexpr int BM = 128, BN = 128, BK = 32, LDS = 40;
    __shared__ __align__(16) __nv_bfloat16 As[2][BM * LDS];
    __shared__ __align__(16) __nv_bfloat16 Bs[2][BN * LDS];

    const int tid = threadIdx.x;
    const int wid = tid >> 5, lane = tid & 31;
    const int wm = wid & 1, wn = wid >> 1;
    const int mOff = wm * 64, nOff = wn * 32;

    size_t offA = 0, offB = 0, offC = 0;
    if (BMODE == 1) {
        const int z = blockIdx.z, b = z / H_, hh = z % H_;
        offA = (size_t)b * N_ * (3 * C_) + (size_t)hh * D_;
        offB = offA;
        offC = (size_t)z * N_ * N_;
    }
    const int row0 = blockIdx.y * BM, col0 = blockIdx.x * BN;
    const float* Ab = A + offA + (size_t)row0 * lda;
    const float* Bb = Bm + offB;
    float* Cb = C + offC;

    const uint32_t aHi = smem_u32(As[0]), aLo = smem_u32(As[1]);
    const uint32_t bHi = smem_u32(Bs[0]), bLo = smem_u32(Bs[1]);

    // ldmatrix lane-derived offsets
    const int lar = lane & 15;            // A row within m16
    const int lac = (lane >> 4) * 8;      // A col 0/8
    const int bq = lane >> 3, br = lane & 7;
    const int brow = (bq >> 1) * 8 + br;  // B row within n16
    const int bcol = (bq & 1) * 8;        // B k col 0/8

    float acc[4][4][4] = {};

    for (int k0 = 0; k0 < K; k0 += BK) {
        // load + split A (128 x 32)
#pragma unroll
        for (int it = 0; it < 4; it++) {
            const int idx = it * 256 + tid;
            const int r = idx >> 3, c4 = (idx & 7) * 4;
            const float4 v = *(const float4*)(Ab + (size_t)r * lda + k0 + c4);
            const float hx = __bfloat162float(__float2bfloat16_rn(v.x));
            const float hy = __bfloat162float(__float2bfloat16_rn(v.y));
            const float hz = __bfloat162float(__float2bfloat16_rn(v.z));
            const float hw = __bfloat162float(__float2bfloat16_rn(v.w));
            *(uint2*)&As[0][r * LDS + c4] = make_uint2(pack_bf16(hx, hy), pack_bf16(hz, hw));
            *(uint2*)&As[1][r * LDS + c4] = make_uint2(pack_bf16(v.x - hx, v.y - hy),
                                                       pack_bf16(v.z - hz, v.w - hw));
        }
        // load + split B (128 x 32), rows are output cols
#pragma unroll
        for (int it = 0; it < 4; it++) {
            const int idx = it * 256 + tid;
            const int r = idx >> 3, c4 = (idx & 7) * 4;
            const float4 v = *(const float4*)(Bb + (size_t)(col0 + r) * ldb + k0 + c4);
            const float hx = __bfloat162float(__float2bfloat16_rn(v.x));
            const float hy = __bfloat162float(__float2bfloat16_rn(v.y));
            const float hz = __bfloat162float(__float2bfloat16_rn(v.z));
            const float hw = __bfloat162float(__float2bfloat16_rn(v.w));
            *(uint2*)&Bs[0][r * LDS + c4] = make_uint2(pack_bf16(hx, hy), pack_bf16(hz, hw));
            *(uint2*)&Bs[1][r * LDS + c4] = make_uint2(pack_bf16(v.x - hx, v.y - hy),
                                                       pack_bf16(v.z - hz, v.w - hw));
        }
        __syncthreads();

#pragma unroll
        for (int term = 0; term < 3; term++) {
            const uint32_t ab = (term == 2) ? aLo : aHi;
            const uint32_t bb = (term == 1) ? bLo : bHi;
#pragma unroll
            for (int kk = 0; kk < BK; kk += 16) {
                uint32_t af[4][4];
#pragma unroll
                for (int mi = 0; mi < 4; mi++)
                    LDSM_X4(af[mi][0], af[mi][1], af[mi][2], af[mi][3],
                            ab + ((mOff + mi * 16 + lar) * LDS + kk + lac) * 2);
                uint32_t bf[4][2];
#pragma unroll
                for (int nb = 0; nb < 2; nb++)
                    LDSM_X4(bf[2 * nb][0], bf[2 * nb][1], bf[2 * nb + 1][0], bf[2 * nb + 1][1],
                            bb + ((nOff + nb * 16 + brow) * LDS + kk + bcol) * 2);
#pragma unroll
                for (int mi = 0; mi < 4; mi++)
#pragma unroll
                    for (int ni = 0; ni < 4; ni++)
                        mma_bf16(acc[mi][ni], af[mi], bf[ni]);
            }
        }
        __syncthreads();
    }

    // epilogue: direct fragment stores
#pragma unroll
    for (int mi = 0; mi < 4; mi++) {
#pragma unroll
        for (int ni = 0; ni < 4; ni++) {
#pragma unroll
            for (int h = 0; h < 2; h++) {   // c0c1 (row), c2c3 (row+8)
                const int r = row0 + mOff + mi * 16 + (lane >> 2) + h * 8;
                const int c = col0 + nOff + ni * 8 + (lane & 3) * 2;
                float v0 = acc[mi][ni][2 * h + 0];
                float v1 = acc[mi][ni][2 * h + 1];
                v0 = apply_epi(v0, EPI, (EPI >= 2) ? bias[c] : 0.f);
                v1 = apply_epi(v1, EPI, (EPI >= 2) ? bias[c + 1] : 0.f);
                const size_t gi = (size_t)r * ldc + c;
                if (EPI == 4) { v0 += res[gi]; v1 += res[gi + 1]; }
                *(float2*)(Cb + gi) = make_float2(v0, v1);
            }
        }
    }
}

// ---------------------------------------------------------------------------
// PV GEMM: O[b,n,h*64+d] = sum_m P[z,n,m] * V[b,m,h*64+d]
// 128x64 tile, BK=32, 8 warps (2x4), warp tile 64x16. V via ldmatrix.trans.
// ---------------------------------------------------------------------------
__global__ void __launch_bounds__(256) mma_pv(
    const float* __restrict__ P, const float* __restrict__ Vm, float* __restrict__ C)
{
    constexpr int BM = 128, BK = 32, LDS = 40, LDV = 72;
    __shared__ __align__(16) __nv_bfloat16 As[2][BM * LDS];
    __shared__ __align__(16) __nv_bfloat16 Vs[2][BK * LDV];

    const int tid = threadIdx.x;
    const int wid = tid >> 5, lane = tid & 31;
    const int wm = wid & 1, wn = wid >> 1;
    const int mOff = wm * 64, nOff = wn * 16;

    const int z = blockIdx.z, b = z / H_, hh = z % H_;
    const int row0 = blockIdx.y * BM;
    const float* Ab = P + (size_t)z * N_ * N_ + (size_t)row0 * N_;
    const float* Vb = Vm + (size_t)b * N_ * (3 * C_) + (size_t)hh * D_;
    float* Cb = C + (size_t)b * N_ * C_ + (size_t)hh * D_;

    const uint32_t aHi = smem_u32(As[0]), aLo = smem_u32(As[1]);
    const uint32_t vHi = smem_u32(Vs[0]), vLo = smem_u32(Vs[1]);

    const int lar = lane & 15, lac = (lane >> 4) * 8;
    const int bq = lane >> 3, br = lane & 7;

    float acc[4][2][4] = {};

    for (int k0 = 0; k0 < N_; k0 += BK) {
        // load + split P (128 x 32)
#pragma unroll
        for (int it = 0; it < 4; it++) {
            const int idx = it * 256 + tid;
            const int r = idx >> 3, c4 = (idx & 7) * 4;
            const float4 v = *(const float4*)(Ab + (size_t)r * N_ + k0 + c4);
            const float hx = __bfloat162float(__float2bfloat16_rn(v.x));
            const float hy = __bfloat162float(__float2bfloat16_rn(v.y));
            const float hz = __bfloat162float(__float2bfloat16_rn(v.z));
            const float hw = __bfloat162float(__float2bfloat16_rn(v.w));
            *(uint2*)&As[0][r * LDS + c4] = make_uint2(pack_bf16(hx, hy), pack_bf16(hz, hw));
            *(uint2*)&As[1][r * LDS + c4] = make_uint2(pack_bf16(v.x - hx, v.y - hy),
                                                       pack_bf16(v.z - hz, v.w - hw));
        }
        // load + split V (32 seq-rows x 64 d-cols), stored un-transposed
#pragma unroll
        for (int it = 0; it < 2; it++) {
            const int idx = it * 256 + tid;
            const int r = idx >> 4, c4 = (idx & 15) * 4;
            const float4 v = *(const float4*)(Vb + (size_t)(k0 + r) * (3 * C_) + c4);
            const float hx = __bfloat162float(__float2bfloat16_rn(v.x));
            const float hy = __bfloat162float(__float2bfloat16_rn(v.y));
            const float hz = __bfloat162float(__float2bfloat16_rn(v.z));
            const float hw = __bfloat162float(__float2bfloat16_rn(v.w));
            *(uint2*)&Vs[0][r * LDV + c4] = make_uint2(pack_bf16(hx, hy), pack_bf16(hz, hw));
            *(uint2*)&Vs[1][r * LDV + c4] = make_uint2(pack_bf16(v.x - hx, v.y - hy),
                                                       pack_bf16(v.z - hz, v.w - hw));
        }
        __syncthreads();

#pragma unroll
        for (int term = 0; term < 3; term++) {
            const uint32_t ab = (term == 2) ? aLo : aHi;
            const uint32_t vb = (term == 1) ? vLo : vHi;
#pragma unroll
            for (int kk = 0; kk < BK; kk += 16) {
                uint32_t af[4][4];
#pragma unroll
                for (int mi = 0; mi < 4; mi++)
                    LDSM_X4(af[mi][0], af[mi][1], af[mi][2], af[mi][3],
                            ab + ((mOff + mi * 16 + lar) * LDS + kk + lac) * 2);
                uint32_t bf[2][2];
                LDSM_X4_T(bf[0][0], bf[0][1], bf[1][0], bf[1][1],
                          vb + ((kk + (bq & 1) * 8 + br) * LDV + nOff + (bq >> 1) * 8) * 2);
#pragma unroll
                for (int mi = 0; mi < 4; mi++)
#pragma unroll
                    for (int ni = 0; ni < 2; ni++)
                        mma_bf16(acc[mi][ni], af[mi], bf[ni]);
            }
        }
        __syncthreads();
    }

#pragma unroll
    for (int mi = 0; mi < 4; mi++)
#pragma unroll
        for (int ni = 0; ni < 2; ni++)
#pragma unroll
            for (int h = 0; h < 2; h++) {
                const int r = row0 + mOff + mi * 16 + (lane >> 2) + h * 8;
                const int c = nOff + ni * 8 + (lane & 3) * 2;
                *(float2*)(Cb + (size_t)r * C_ + c) =
                    make_float2(acc[mi][ni][2 * h + 0], acc[mi][ni][2 * h + 1]);
            }
}

// ---------------------------------------------------------------------------
// Launch sequence
// ---------------------------------------------------------------------------
extern "C" void kernel_launch(void* const* d_in, const int* in_sizes, int n_in,
                              void* d_out, int out_size) {
    (void)in_sizes; (void)n_in; (void)out_size;
    const float* x      = (const float*)d_in[0];
    const float* ln1_w  = (const float*)d_in[1];
    const float* ln1_b  = (const float*)d_in[2];
    const float* qkv_w  = (const float*)d_in[3];
    const float* proj_w = (const float*)d_in[4];
    const float* proj_b = (const float*)d_in[5];
    const float* ln2_w  = (const float*)d_in[6];
    const float* ln2_b  = (const float*)d_in[7];
    const float* fc1_w  = (const float*)d_in[8];
    const float* fc1_b  = (const float*)d_in[9];
    const float* fc2_w  = (const float*)d_in[10];
    const float* fc2_b  = (const float*)d_in[11];
    float* out = (float*)d_out;

    float *h, *qkv, *S, *o, *xres, *fc1;
    cudaGetSymbolAddress((void**)&h,    g_h);
    cudaGetSymbolAddress((void**)&qkv,  g_qkv);
    cudaGetSymbolAddress((void**)&S,    g_S);
    cudaGetSymbolAddress((void**)&o,    g_o);
    cudaGetSymbolAddress((void**)&xres, g_xres);
    cudaGetSymbolAddress((void**)&fc1,  g_fc1);

    // 1. LN1
    ln_kernel<<<M_, 256>>>(x, ln1_w, ln1_b, h);
    // 2. QKV: [16384, 2304] = h @ qkv_w^T
    mma_gemm<0, 0><<<dim3(18, 128, 1), 256>>>(h, qkv_w, nullptr, nullptr, qkv,
                                              C_, C_, C_, 3 * C_);
    // 3. S = (Q @ K^T) * 0.125 per (b,h)
    mma_gemm<1, 1><<<dim3(4, 4, BH_), 256>>>(qkv, qkv + C_, nullptr, nullptr, S,
                                             D_, 3 * C_, 3 * C_, N_);
    // 4. softmax
    softmax_kernel<<<BH_ * N_, 128>>>(S);
    // 5. O = P @ V
    mma_pv<<<dim3(1, 4, BH_), 256>>>(S, qkv + 2 * C_, o);
    // 6. xres = 2*(o @ proj_w^T + proj_b)
    mma_gemm<2, 0><<<dim3(6, 128, 1), 256>>>(o, proj_w, proj_b, nullptr, xres,
                                             C_, C_, C_, C_);
    // 7. LN2
    ln_kernel<<<M_, 256>>>(xres, ln2_w, ln2_b, h);
    // 8. fc1 + GELU
    mma_gemm<3, 0><<<dim3(24, 128, 1), 256>>>(h, fc1_w, fc1_b, nullptr, fc1,
                                              C_, C_, C_, HID_);
    // 9. out = xres + fc1 @ fc2_w^T + fc2_b
    mma_gemm<4, 0><<<dim3(6, 128, 1), 256>>>(fc1, fc2_w, fc2_b, xres, out,
                                             HID_, HID_, HID_, C_);
}

// round 5
// speedup vs baseline: 2.6675x; 1.1788x over previous
#include <cuda_runtime.h>
#include <cuda_bf16.h>
#include <math.h>
#include <stdint.h>

namespace {
constexpr int B_   = 32;
constexpr int N_   = 512;
constexpr int C_   = 768;
constexpr int H_   = 12;
constexpr int D_   = 64;
constexpr int HID_ = 3072;
constexpr int M_   = B_ * N_;   // 16384
constexpr int BH_  = B_ * H_;   // 384
}

// fp32 scratch
__device__ float g_S[(size_t)BH_ * N_ * N_];     // scores; post-softmax holds P hi/lo bf16 in place
__device__ float g_xres[M_ * C_];
// bf16 hi/lo planes
__device__ __nv_bfloat16 g_h_hi[M_ * C_],      g_h_lo[M_ * C_];
__device__ __nv_bfloat16 g_qkv_hi[M_ * 3 * C_],g_qkv_lo[M_ * 3 * C_];
__device__ __nv_bfloat16 g_o_hi[M_ * C_],      g_o_lo[M_ * C_];
__device__ __nv_bfloat16 g_f1_hi[M_ * HID_],   g_f1_lo[M_ * HID_];
__device__ __nv_bfloat16 g_qkvw_hi[3 * C_ * C_], g_qkvw_lo[3 * C_ * C_];
__device__ __nv_bfloat16 g_projw_hi[C_ * C_],  g_projw_lo[C_ * C_];
__device__ __nv_bfloat16 g_fc1w_hi[HID_ * C_], g_fc1w_lo[HID_ * C_];
__device__ __nv_bfloat16 g_fc2w_hi[C_ * HID_], g_fc2w_lo[C_ * HID_];

// ---------------------------------------------------------------------------
// helpers
// ---------------------------------------------------------------------------
__device__ __forceinline__ uint32_t smem_u32(const void* p) {
    uint32_t a;
    asm("{ .reg .u64 t; cvta.to.shared.u64 t, %1; cvt.u32.u64 %0, t; }" : "=r"(a) : "l"(p));
    return a;
}
#define CP_ASYNC8(dst, src) \
    asm volatile("cp.async.ca.shared.global [%0], [%1], 8;" :: "r"(dst), "l"(src))
#define CP_COMMIT() asm volatile("cp.async.commit_group;" ::: "memory")
#define CP_WAIT1()  asm volatile("cp.async.wait_group 1;" ::: "memory")

#define LDSM_X4(r0, r1, r2, r3, addr)                                             \
    asm volatile("ldmatrix.sync.aligned.m8n8.x4.shared.b16 {%0,%1,%2,%3}, [%4];"  \
                 : "=r"(r0), "=r"(r1), "=r"(r2), "=r"(r3) : "r"(addr))
#define LDSM_X4_T(r0, r1, r2, r3, addr)                                                \
    asm volatile("ldmatrix.sync.aligned.m8n8.x4.trans.shared.b16 {%0,%1,%2,%3}, [%4];" \
                 : "=r"(r0), "=r"(r1), "=r"(r2), "=r"(r3) : "r"(addr))
__device__ __forceinline__ void mma_bf16(float* c, const uint32_t* a, const uint32_t* b) {
    asm volatile(
        "mma.sync.aligned.m16n8k16.row.col.f32.bf16.bf16.f32 "
        "{%0,%1,%2,%3}, {%4,%5,%6,%7}, {%8,%9}, {%0,%1,%2,%3};"
        : "+f"(c[0]), "+f"(c[1]), "+f"(c[2]), "+f"(c[3])
        : "r"(a[0]), "r"(a[1]), "r"(a[2]), "r"(a[3]), "r"(b[0]), "r"(b[1]));
}
__device__ __forceinline__ void split_store(__nv_bfloat16* hi, __nv_bfloat16* lo,
                                            size_t gi, float v0, float v1) {
    const __nv_bfloat16 h0 = __float2bfloat16_rn(v0);
    const __nv_bfloat16 h1 = __float2bfloat16_rn(v1);
    __nv_bfloat162 hp; hp.x = h0; hp.y = h1;
    __nv_bfloat162 lp;
    lp.x = __float2bfloat16_rn(v0 - __bfloat162float(h0));
    lp.y = __float2bfloat16_rn(v1 - __bfloat162float(h1));
    *(__nv_bfloat162*)(hi + gi) = hp;
    *(__nv_bfloat162*)(lo + gi) = lp;
}

// ---------------------------------------------------------------------------
// weight convert: fp32 -> bf16 hi/lo planes
// ---------------------------------------------------------------------------
__global__ void cvt_kernel(const float* __restrict__ src, __nv_bfloat16* __restrict__ hi,
                           __nv_bfloat16* __restrict__ lo, int n4) {
    const int i = blockIdx.x * 256 + threadIdx.x;
    if (i >= n4) return;
    const float4 v = ((const float4*)src)[i];
    split_store(hi, lo, (size_t)i * 4, v.x, v.y);
    split_store(hi, lo, (size_t)i * 4 + 2, v.z, v.w);
}

// ---------------------------------------------------------------------------
// LayerNorm -> bf16 hi/lo planes
// ---------------------------------------------------------------------------
__global__ void ln_bf_kernel(const float* __restrict__ x, const float* __restrict__ w,
                             const float* __restrict__ bia,
                             __nv_bfloat16* __restrict__ hi, __nv_bfloat16* __restrict__ lo) {
    __shared__ float red[256];
    const int row = blockIdx.x;
    const int t = threadIdx.x;
    const float* xr = x + (size_t)row * C_;
    float v[3];
    float s = 0.f, s2 = 0.f;
#pragma unroll
    for (int j = 0; j < 3; j++) { v[j] = xr[t + 256 * j]; s += v[j]; s2 += v[j] * v[j]; }
    red[t] = s; __syncthreads();
    for (int o = 128; o > 0; o >>= 1) { if (t < o) red[t] += red[t + o]; __syncthreads(); }
    const float mean = red[0] * (1.f / C_);
    __syncthreads();
    red[t] = s2; __syncthreads();
    for (int o = 128; o > 0; o >>= 1) { if (t < o) red[t] += red[t + o]; __syncthreads(); }
    const float var = red[0] * (1.f / C_) - mean * mean;
    const float rstd = rsqrtf(var + 1e-5f);
#pragma unroll
    for (int j = 0; j < 3; j++) {
        const int c = t + 256 * j;
        const float y = (v[j] - mean) * rstd * w[c] + bia[c];
        const size_t gi = (size_t)row * C_ + c;
        const __nv_bfloat16 h = __float2bfloat16_rn(y);
        hi[gi] = h;
        lo[gi] = __float2bfloat16_rn(y - __bfloat162float(h));
    }
}

// ---------------------------------------------------------------------------
// Softmax: fp32 row in, bf16 hi/lo row out IN PLACE (row 2048B = [512 hi][512 lo])
// ---------------------------------------------------------------------------
__global__ void softmax_kernel(float* __restrict__ S) {
    __shared__ float red[128];
    const size_t row = blockIdx.x;
    float* r = S + row * N_;
    const int t = threadIdx.x;
    float v[4];
    float m = -1e30f;
#pragma unroll
    for (int j = 0; j < 4; j++) { v[j] = r[t + 128 * j]; m = fmaxf(m, v[j]); }
    red[t] = m; __syncthreads();
    for (int o = 64; o > 0; o >>= 1) { if (t < o) red[t] = fmaxf(red[t], red[t + o]); __syncthreads(); }
    m = red[0]; __syncthreads();
    float s = 0.f;
#pragma unroll
    for (int j = 0; j < 4; j++) { v[j] = __expf(v[j] - m); s += v[j]; }
    red[t] = s; __syncthreads();
    for (int o = 64; o > 0; o >>= 1) { if (t < o) red[t] += red[t + o]; __syncthreads(); }
    const float inv = 1.f / red[0];
    __nv_bfloat16* hi = (__nv_bfloat16*)r;
    __nv_bfloat16* lo = hi + N_;
#pragma unroll
    for (int j = 0; j < 4; j++) {
        const int c = t + 128 * j;
        const float p = v[j] * inv;
        const __nv_bfloat16 h = __float2bfloat16_rn(p);
        hi[c] = h;
        lo[c] = __float2bfloat16_rn(p - __bfloat162float(h));
    }
}

// ---------------------------------------------------------------------------
// bf16-split HMMA GEMM with cp.async 2-stage pipeline.
// C[M,N] = A[M,K] @ B[N,K]^T, A/B given as bf16 hi/lo planes.
// 128x128 tile, BK=32, 8 warps, warp tile 64x32.
// EPI: 0 -> hi/lo planes; 1 -> *0.125 fp32; 2 -> 2*(v+bias) fp32;
//      3 -> gelu(v+bias) -> hi/lo planes; 4 -> v+bias+res fp32
// BMODE: 0 plain; 1 per-(b,h) QK^T offsets
// ---------------------------------------------------------------------------
template <int EPI, int BMODE>
__global__ void __launch_bounds__(256) mma_gemm2(
    const __nv_bfloat16* __restrict__ Ahi, const __nv_bfloat16* __restrict__ Alo,
    const __nv_bfloat16* __restrict__ Bhi, const __nv_bfloat16* __restrict__ Blo,
    const float* __restrict__ bias, const float* __restrict__ res,
    float* __restrict__ Cf, __nv_bfloat16* __restrict__ Chi, __nv_bfloat16* __restrict__ Clo,
    int K, int lda, int ldb, int ldc)
{
    constexpr int LDS = 40;
    constexpr uint32_t PLANE_B = 128 * LDS * 2;   // 10240
    constexpr uint32_t STAGE_B = 4 * PLANE_B;     // 40960
    extern __shared__ __nv_bfloat16 sm[];
    const uint32_t sbase = smem_u32(sm);

    const int tid = threadIdx.x;
    const int wid = tid >> 5, lane = tid & 31;
    const int wm = wid & 1, wn = wid >> 1;
    const int mOff = wm * 64, nOff = wn * 32;

    size_t offA = 0, offB = 0, offC = 0;
    if (BMODE == 1) {
        const int z = blockIdx.z, b = z / H_, hh = z % H_;
        offA = (size_t)b * N_ * (3 * C_) + (size_t)hh * D_;
        offB = offA;
        offC = (size_t)z * N_ * N_;
    }
    const int row0 = blockIdx.y * 128, col0 = blockIdx.x * 128;
    const __nv_bfloat16* pl[4] = {
        Ahi + offA + (size_t)row0 * lda, Alo + offA + (size_t)row0 * lda,
        Bhi + offB + (size_t)col0 * ldb, Blo + offB + (size_t)col0 * ldb };

    const int lr = tid >> 3, lc4 = (tid & 7) * 4;  // per-thread base for copies

    auto issue = [&](int c, int stage) {
        const int k0 = c * 32;
        const uint32_t sst = sbase + stage * STAGE_B;
#pragma unroll
        for (int p = 0; p < 4; p++) {
            const __nv_bfloat16* base = pl[p];
            const int ld = (p < 2) ? lda : ldb;
            const uint32_t sp = sst + p * PLANE_B;
#pragma unroll
            for (int i = 0; i < 4; i++) {
                const int r = i * 32 + lr;
                CP_ASYNC8(sp + (uint32_t)(r * 80 + lc4 * 2),
                          base + (size_t)r * ld + k0 + lc4);
            }
        }
    };

    const int lar = lane & 15, lac = (lane >> 4) * 8;
    const int bq = lane >> 3, br = lane & 7;
    const int brow = (bq >> 1) * 8 + br, bcol = (bq & 1) * 8;

    float acc[4][4][4] = {};

    const int chunks = K / 32;
    issue(0, 0);
    CP_COMMIT();
    for (int c = 0; c < chunks; c++) {
        if (c + 1 < chunks) issue(c + 1, (c + 1) & 1);
        CP_COMMIT();
        CP_WAIT1();
        __syncthreads();
        const uint32_t sst = sbase + (c & 1) * STAGE_B;
        const uint32_t aHi = sst, aLo = sst + PLANE_B;
        const uint32_t bHi = sst + 2 * PLANE_B, bLo = sst + 3 * PLANE_B;
#pragma unroll
        for (int term = 0; term < 3; term++) {
            const uint32_t ab = (term == 2) ? aLo : aHi;
            const uint32_t bb = (term == 1) ? bLo : bHi;
#pragma unroll
            for (int kk = 0; kk < 32; kk += 16) {
                uint32_t af[4][4];
#pragma unroll
                for (int mi = 0; mi < 4; mi++)
                    LDSM_X4(af[mi][0], af[mi][1], af[mi][2], af[mi][3],
                            ab + (uint32_t)(((mOff + mi * 16 + lar) * LDS + kk + lac) * 2));
                uint32_t bf[4][2];
#pragma unroll
                for (int nb = 0; nb < 2; nb++)
                    LDSM_X4(bf[2 * nb][0], bf[2 * nb][1], bf[2 * nb + 1][0], bf[2 * nb + 1][1],
                            bb + (uint32_t)(((nOff + nb * 16 + brow) * LDS + kk + bcol) * 2));
#pragma unroll
                for (int mi = 0; mi < 4; mi++)
#pragma unroll
                    for (int ni = 0; ni < 4; ni++)
                        mma_bf16(acc[mi][ni], af[mi], bf[ni]);
            }
        }
        __syncthreads();
    }

    // epilogue
#pragma unroll
    for (int mi = 0; mi < 4; mi++) {
#pragma unroll
        for (int ni = 0; ni < 4; ni++) {
#pragma unroll
            for (int h = 0; h < 2; h++) {
                const int r = row0 + mOff + mi * 16 + (lane >> 2) + h * 8;
                const int c = col0 + nOff + ni * 8 + (lane & 3) * 2;
                float v0 = acc[mi][ni][2 * h + 0];
                float v1 = acc[mi][ni][2 * h + 1];
                const size_t gi = offC + (size_t)r * ldc + c;
                if (EPI == 0) {
                    split_store(Chi, Clo, gi, v0, v1);
                } else if (EPI == 1) {
                    *(float2*)(Cf + gi) = make_float2(v0 * 0.125f, v1 * 0.125f);
                } else if (EPI == 2) {
                    *(float2*)(Cf + gi) = make_float2(2.f * (v0 + bias[c]), 2.f * (v1 + bias[c + 1]));
                } else if (EPI == 3) {
                    v0 += bias[c];  v1 += bias[c + 1];
                    v0 = 0.5f * v0 * (1.f + erff(v0 * 0.70710678118654752f));
                    v1 = 0.5f * v1 * (1.f + erff(v1 * 0.70710678118654752f));
                    split_store(Chi, Clo, gi, v0, v1);
                } else {  // EPI 4
                    v0 += bias[c] + res[gi];
                    v1 += bias[c + 1] + res[gi + 1];
                    *(float2*)(Cf + gi) = make_float2(v0, v1);
                }
            }
        }
    }
}

// ---------------------------------------------------------------------------
// PV GEMM: o = P @ V.  P hi/lo packed in S rows (2048B = [512 hi][512 lo]),
// V from qkv planes (trans ldmatrix). 128x64 tile, BK=32, warp tile 64x16.
// Output: o hi/lo planes.
// ---------------------------------------------------------------------------
__global__ void __launch_bounds__(256) mma_pv2(
    const float* __restrict__ S,
    const __nv_bfloat16* __restrict__ Vhi, const __nv_bfloat16* __restrict__ Vlo,
    __nv_bfloat16* __restrict__ Ohi, __nv_bfloat16* __restrict__ Olo)
{
    constexpr int LDS = 40, LDV = 72;
    constexpr uint32_t P_PLANE = 128 * LDS * 2;                 // 10240
    constexpr uint32_t V_PLANE = 32 * LDV * 2;                  // 4608
    constexpr uint32_t STAGE_B = 2 * P_PLANE + 2 * V_PLANE;     // 29696
    extern __shared__ __nv_bfloat16 sm[];
    const uint32_t sbase = smem_u32(sm);

    const int tid = threadIdx.x;
    const int wid = tid >> 5, lane = tid & 31;
    const int wm = wid & 1, wn = wid >> 1;
    const int mOff = wm * 64, nOff = wn * 16;

    const int z = blockIdx.z, b = z / H_, hh = z % H_;
    const int row0 = blockIdx.y * 128;
    const char* Pbase = (const char*)S + ((size_t)z * N_ + row0) * 2048;
    const __nv_bfloat16* Vb_hi = Vhi + (size_t)b * N_ * (3 * C_) + 2 * C_ + (size_t)hh * D_;
    const __nv_bfloat16* Vb_lo = Vlo + (size_t)b * N_ * (3 * C_) + 2 * C_ + (size_t)hh * D_;
    const size_t offO = (size_t)b * N_ * C_ + (size_t)hh * D_;

    const int lr = tid >> 3, lc4 = (tid & 7) * 4;      // P copy map (128x32)
    const int vr = tid >> 4, vc4 = (tid & 15) * 4;     // V copy map (32x64)

    auto issue = [&](int c, int stage) {
        const int k0 = c * 32;
        const uint32_t sst = sbase + stage * STAGE_B;
#pragma unroll
        for (int p = 0; p < 2; p++) {
            const uint32_t sp = sst + p * P_PLANE;
#pragma unroll
            for (int i = 0; i < 4; i++) {
                const int r = i * 32 + lr;
                CP_ASYNC8(sp + (uint32_t)(r * 80 + lc4 * 2),
                          Pbase + (size_t)r * 2048 + p * 1024 + (k0 + lc4) * 2);
            }
        }
#pragma unroll
        for (int p = 0; p < 2; p++) {
            const __nv_bfloat16* base = p ? Vb_lo : Vb_hi;
            const uint32_t sp = sst + 2 * P_PLANE + p * V_PLANE;
#pragma unroll
            for (int i = 0; i < 2; i++) {
                const int r = i * 16 + vr;
                CP_ASYNC8(sp + (uint32_t)(r * 144 + vc4 * 2),
                          base + (size_t)(k0 + r) * (3 * C_) + vc4);
            }
        }
    };

    const int lar = lane & 15, lac = (lane >> 4) * 8;
    const int bq = lane >> 3, br = lane & 7;

    float acc[4][2][4] = {};

    issue(0, 0);
    CP_COMMIT();
    for (int c = 0; c < N_ / 32; c++) {
        if (c + 1 < N_ / 32) issue(c + 1, (c + 1) & 1);
        CP_COMMIT();
        CP_WAIT1();
        __syncthreads();
        const uint32_t sst = sbase + (c & 1) * STAGE_B;
        const uint32_t aHi = sst, aLo = sst + P_PLANE;
        const uint32_t vHi = sst + 2 * P_PLANE, vLo = vHi + V_PLANE;
#pragma unroll
        for (int term = 0; term < 3; term++) {
            const uint32_t ab = (term == 2) ? aLo : aHi;
            const uint32_t vb = (term == 1) ? vLo : vHi;
#pragma unroll
            for (int kk = 0; kk < 32; kk += 16) {
                uint32_t af[4][4];
#pragma unroll
                for (int mi = 0; mi < 4; mi++)
                    LDSM_X4(af[mi][0], af[mi][1], af[mi][2], af[mi][3],
                            ab + (uint32_t)(((mOff + mi * 16 + lar) * LDS + kk + lac) * 2));
                uint32_t bf[2][2];
                LDSM_X4_T(bf[0][0], bf[0][1], bf[1][0], bf[1][1],
                          vb + (uint32_t)(((kk + (bq & 1) * 8 + br) * LDV + nOff + (bq >> 1) * 8) * 2));
#pragma unroll
                for (int mi = 0; mi < 4; mi++)
#pragma unroll
                    for (int ni = 0; ni < 2; ni++)
                        mma_bf16(acc[mi][ni], af[mi], bf[ni]);
            }
        }
        __syncthreads();
    }

#pragma unroll
    for (int mi = 0; mi < 4; mi++)
#pragma unroll
        for (int ni = 0; ni < 2; ni++)
#pragma unroll
            for (int h = 0; h < 2; h++) {
                const int r = row0 + mOff + mi * 16 + (lane >> 2) + h * 8;
                const int c = nOff + ni * 8 + (lane & 3) * 2;
                split_store(Ohi, Olo, offO + (size_t)r * C_ + c,
                            acc[mi][ni][2 * h + 0], acc[mi][ni][2 * h + 1]);
            }
}

// ---------------------------------------------------------------------------
// Launch sequence
// ---------------------------------------------------------------------------
extern "C" void kernel_launch(void* const* d_in, const int* in_sizes, int n_in,
                              void* d_out, int out_size) {
    (void)in_sizes; (void)n_in; (void)out_size;
    const float* x      = (const float*)d_in[0];
    const float* ln1_w  = (const float*)d_in[1];
    const float* ln1_b  = (const float*)d_in[2];
    const float* qkv_w  = (const float*)d_in[3];
    const float* proj_w = (const float*)d_in[4];
    const float* proj_b = (const float*)d_in[5];
    const float* ln2_w  = (const float*)d_in[6];
    const float* ln2_b  = (const float*)d_in[7];
    const float* fc1_w  = (const float*)d_in[8];
    const float* fc1_b  = (const float*)d_in[9];
    const float* fc2_w  = (const float*)d_in[10];
    const float* fc2_b  = (const float*)d_in[11];
    float* out = (float*)d_out;

    float *S, *xres;
    __nv_bfloat16 *h_hi, *h_lo, *qkv_hi, *qkv_lo, *o_hi, *o_lo, *f1_hi, *f1_lo;
    __nv_bfloat16 *qw_hi, *qw_lo, *pw_hi, *pw_lo, *f1w_hi, *f1w_lo, *f2w_hi, *f2w_lo;
    cudaGetSymbolAddress((void**)&S,      g_S);
    cudaGetSymbolAddress((void**)&xres,   g_xres);
    cudaGetSymbolAddress((void**)&h_hi,   g_h_hi);   cudaGetSymbolAddress((void**)&h_lo,   g_h_lo);
    cudaGetSymbolAddress((void**)&qkv_hi, g_qkv_hi); cudaGetSymbolAddress((void**)&qkv_lo, g_qkv_lo);
    cudaGetSymbolAddress((void**)&o_hi,   g_o_hi);   cudaGetSymbolAddress((void**)&o_lo,   g_o_lo);
    cudaGetSymbolAddress((void**)&f1_hi,  g_f1_hi);  cudaGetSymbolAddress((void**)&f1_lo,  g_f1_lo);
    cudaGetSymbolAddress((void**)&qw_hi,  g_qkvw_hi);  cudaGetSymbolAddress((void**)&qw_lo,  g_qkvw_lo);
    cudaGetSymbolAddress((void**)&pw_hi,  g_projw_hi); cudaGetSymbolAddress((void**)&pw_lo,  g_projw_lo);
    cudaGetSymbolAddress((void**)&f1w_hi, g_fc1w_hi);  cudaGetSymbolAddress((void**)&f1w_lo, g_fc1w_lo);
    cudaGetSymbolAddress((void**)&f2w_hi, g_fc2w_hi);  cudaGetSymbolAddress((void**)&f2w_lo, g_fc2w_lo);

    constexpr int SMEM_GEMM = 2 * 4 * 128 * 40 * 2;   // 81920
    constexpr int SMEM_PV   = 2 * (2 * 128 * 40 + 2 * 32 * 72) * 2;  // 59392
    cudaFuncSetAttribute(mma_gemm2<0, 0>, cudaFuncAttributeMaxDynamicSharedMemorySize, SMEM_GEMM);
    cudaFuncSetAttribute(mma_gemm2<1, 1>, cudaFuncAttributeMaxDynamicSharedMemorySize, SMEM_GEMM);
    cudaFuncSetAttribute(mma_gemm2<2, 0>, cudaFuncAttributeMaxDynamicSharedMemorySize, SMEM_GEMM);
    cudaFuncSetAttribute(mma_gemm2<3, 0>, cudaFuncAttributeMaxDynamicSharedMemorySize, SMEM_GEMM);
    cudaFuncSetAttribute(mma_gemm2<4, 0>, cudaFuncAttributeMaxDynamicSharedMemorySize, SMEM_GEMM);
    cudaFuncSetAttribute(mma_pv2,         cudaFuncAttributeMaxDynamicSharedMemorySize, SMEM_PV);

    // 0. pre-split weights to bf16 hi/lo
    cvt_kernel<<<(3 * C_ * C_ / 4 + 255) / 256, 256>>>(qkv_w,  qw_hi,  qw_lo,  3 * C_ * C_ / 4);
    cvt_kernel<<<(C_ * C_ / 4 + 255) / 256, 256>>>(proj_w, pw_hi,  pw_lo,  C_ * C_ / 4);
    cvt_kernel<<<(HID_ * C_ / 4 + 255) / 256, 256>>>(fc1_w,  f1w_hi, f1w_lo, HID_ * C_ / 4);
    cvt_kernel<<<(C_ * HID_ / 4 + 255) / 256, 256>>>(fc2_w,  f2w_hi, f2w_lo, C_ * HID_ / 4);

    // 1. LN1 -> h planes
    ln_bf_kernel<<<M_, 256>>>(x, ln1_w, ln1_b, h_hi, h_lo);
    // 2. QKV -> qkv planes
    mma_gemm2<0, 0><<<dim3(18, 128, 1), 256, SMEM_GEMM>>>(
        h_hi, h_lo, qw_hi, qw_lo, nullptr, nullptr, nullptr, qkv_hi, qkv_lo,
        C_, C_, C_, 3 * C_);
    // 3. S = (Q @ K^T) * 0.125 per (b,h)
    mma_gemm2<1, 1><<<dim3(4, 4, BH_), 256, SMEM_GEMM>>>(
        qkv_hi, qkv_lo, qkv_hi + C_, qkv_lo + C_, nullptr, nullptr, S, nullptr, nullptr,
        D_, 3 * C_, 3 * C_, N_);
    // 4. softmax -> P hi/lo in place
    softmax_kernel<<<BH_ * N_, 128>>>(S);
    // 5. O = P @ V -> o planes
    mma_pv2<<<dim3(1, 4, BH_), 256, SMEM_PV>>>(S, qkv_hi, qkv_lo, o_hi, o_lo);
    // 6. xres = 2*(o @ proj_w^T + proj_b)
    mma_gemm2<2, 0><<<dim3(6, 128, 1), 256, SMEM_GEMM>>>(
        o_hi, o_lo, pw_hi, pw_lo, proj_b, nullptr, xres, nullptr, nullptr,
        C_, C_, C_, C_);
    // 7. LN2 -> h planes
    ln_bf_kernel<<<M_, 256>>>(xres, ln2_w, ln2_b, h_hi, h_lo);
    // 8. fc1 + GELU -> f1 planes
    mma_gemm2<3, 0><<<dim3(24, 128, 1), 256, SMEM_GEMM>>>(
        h_hi, h_lo, f1w_hi, f1w_lo, fc1_b, nullptr, nullptr, f1_hi, f1_lo,
        C_, C_, C_, HID_);
    // 9. out = xres + f1 @ fc2_w^T + fc2_b
    mma_gemm2<4, 0><<<dim3(6, 128, 1), 256, SMEM_GEMM>>>(
        f1_hi, f1_lo, f2w_hi, f2w_lo, fc2_b, xres, out, nullptr, nullptr,
        HID_, HID_, HID_, C_);
}

// round 6
// speedup vs baseline: 2.9936x; 1.1222x over previous
#include <cuda_runtime.h>
#include <cuda_bf16.h>
#include <math.h>
#include <stdint.h>

namespace {
constexpr int B_   = 32;
constexpr int N_   = 512;
constexpr int C_   = 768;
constexpr int H_   = 12;
constexpr int D_   = 64;
constexpr int HID_ = 3072;
constexpr int M_   = B_ * N_;   // 16384
constexpr int BH_  = B_ * H_;   // 384
}

// fp32 scratch
__device__ float g_xres[M_ * C_];
// bf16 hi/lo planes
__device__ __nv_bfloat16 g_h_hi[M_ * C_],      g_h_lo[M_ * C_];
__device__ __nv_bfloat16 g_qkv_hi[M_ * 3 * C_],g_qkv_lo[M_ * 3 * C_];
__device__ __nv_bfloat16 g_o_hi[M_ * C_],      g_o_lo[M_ * C_];
__device__ __nv_bfloat16 g_f1_hi[M_ * HID_],   g_f1_lo[M_ * HID_];
__device__ __nv_bfloat16 g_qkvw_hi[3 * C_ * C_], g_qkvw_lo[3 * C_ * C_];
__device__ __nv_bfloat16 g_projw_hi[C_ * C_],  g_projw_lo[C_ * C_];
__device__ __nv_bfloat16 g_fc1w_hi[HID_ * C_], g_fc1w_lo[HID_ * C_];
__device__ __nv_bfloat16 g_fc2w_hi[C_ * HID_], g_fc2w_lo[C_ * HID_];

// ---------------------------------------------------------------------------
// helpers
// ---------------------------------------------------------------------------
__device__ __forceinline__ uint32_t smem_u32(const void* p) {
    uint32_t a;
    asm("{ .reg .u64 t; cvta.to.shared.u64 t, %1; cvt.u32.u64 %0, t; }" : "=r"(a) : "l"(p));
    return a;
}
#define CP_ASYNC8(dst, src) \
    asm volatile("cp.async.ca.shared.global [%0], [%1], 8;" :: "r"(dst), "l"(src))
#define CP_COMMIT() asm volatile("cp.async.commit_group;" ::: "memory")
#define CP_WAIT1()  asm volatile("cp.async.wait_group 1;" ::: "memory")

#define LDSM_X4(r0, r1, r2, r3, addr)                                             \
    asm volatile("ldmatrix.sync.aligned.m8n8.x4.shared.b16 {%0,%1,%2,%3}, [%4];"  \
                 : "=r"(r0), "=r"(r1), "=r"(r2), "=r"(r3) : "r"(addr))
#define LDSM_X4_T(r0, r1, r2, r3, addr)                                                \
    asm volatile("ldmatrix.sync.aligned.m8n8.x4.trans.shared.b16 {%0,%1,%2,%3}, [%4];" \
                 : "=r"(r0), "=r"(r1), "=r"(r2), "=r"(r3) : "r"(addr))
__device__ __forceinline__ void mma_bf16(float* c, const uint32_t* a, const uint32_t* b) {
    asm volatile(
        "mma.sync.aligned.m16n8k16.row.col.f32.bf16.bf16.f32 "
        "{%0,%1,%2,%3}, {%4,%5,%6,%7}, {%8,%9}, {%0,%1,%2,%3};"
        : "+f"(c[0]), "+f"(c[1]), "+f"(c[2]), "+f"(c[3])
        : "r"(a[0]), "r"(a[1]), "r"(a[2]), "r"(a[3]), "r"(b[0]), "r"(b[1]));
}
__device__ __forceinline__ uint32_t pack2(float x, float y) {
    __nv_bfloat162 t = __floats2bfloat162_rn(x, y);
    return *reinterpret_cast<uint32_t*>(&t);
}
__device__ __forceinline__ void split_pair(float x, float y, uint32_t& hi, uint32_t& lo) {
    const __nv_bfloat16 hx = __float2bfloat16_rn(x);
    const __nv_bfloat16 hy = __float2bfloat16_rn(y);
    __nv_bfloat162 hp; hp.x = hx; hp.y = hy;
    hi = *reinterpret_cast<uint32_t*>(&hp);
    lo = pack2(x - __bfloat162float(hx), y - __bfloat162float(hy));
}
__device__ __forceinline__ void split_store(__nv_bfloat16* hi, __nv_bfloat16* lo,
                                            size_t gi, float v0, float v1) {
    uint32_t h, l;
    split_pair(v0, v1, h, l);
    *(uint32_t*)(hi + gi) = h;
    *(uint32_t*)(lo + gi) = l;
}

// ---------------------------------------------------------------------------
// weight convert: fp32 -> bf16 hi/lo planes
// ---------------------------------------------------------------------------
__global__ void cvt_kernel(const float* __restrict__ src, __nv_bfloat16* __restrict__ hi,
                           __nv_bfloat16* __restrict__ lo, int n4) {
    const int i = blockIdx.x * 256 + threadIdx.x;
    if (i >= n4) return;
    const float4 v = ((const float4*)src)[i];
    split_store(hi, lo, (size_t)i * 4, v.x, v.y);
    split_store(hi, lo, (size_t)i * 4 + 2, v.z, v.w);
}

// ---------------------------------------------------------------------------
// LayerNorm -> bf16 hi/lo planes
// ---------------------------------------------------------------------------
__global__ void ln_bf_kernel(const float* __restrict__ x, const float* __restrict__ w,
                             const float* __restrict__ bia,
                             __nv_bfloat16* __restrict__ hi, __nv_bfloat16* __restrict__ lo) {
    __shared__ float red[256];
    const int row = blockIdx.x;
    const int t = threadIdx.x;
    const float* xr = x + (size_t)row * C_;
    float v[3];
    float s = 0.f, s2 = 0.f;
#pragma unroll
    for (int j = 0; j < 3; j++) { v[j] = xr[t + 256 * j]; s += v[j]; s2 += v[j] * v[j]; }
    red[t] = s; __syncthreads();
    for (int o = 128; o > 0; o >>= 1) { if (t < o) red[t] += red[t + o]; __syncthreads(); }
    const float mean = red[0] * (1.f / C_);
    __syncthreads();
    red[t] = s2; __syncthreads();
    for (int o = 128; o > 0; o >>= 1) { if (t < o) red[t] += red[t + o]; __syncthreads(); }
    const float var = red[0] * (1.f / C_) - mean * mean;
    const float rstd = rsqrtf(var + 1e-5f);
#pragma unroll
    for (int j = 0; j < 3; j++) {
        const int c = t + 256 * j;
        const float y = (v[j] - mean) * rstd * w[c] + bia[c];
        const size_t gi = (size_t)row * C_ + c;
        const __nv_bfloat16 h = __float2bfloat16_rn(y);
        hi[gi] = h;
        lo[gi] = __float2bfloat16_rn(y - __bfloat162float(h));
    }
}

// ---------------------------------------------------------------------------
// Flash attention: per CTA one (b,h) x 128 Q rows. 8 warps x m16.
// S/P live in registers; online softmax; 3-term bf16 split throughout.
// Inputs: qkv hi/lo planes. Outputs: o hi/lo planes.
// ---------------------------------------------------------------------------
__global__ void __launch_bounds__(256) flash_kernel(
    const __nv_bfloat16* __restrict__ QKVhi, const __nv_bfloat16* __restrict__ QKVlo,
    __nv_bfloat16* __restrict__ Ohi, __nv_bfloat16* __restrict__ Olo)
{
    constexpr int LDS = 72;                         // elems per padded row
    constexpr uint32_t QPLANE  = 128 * LDS * 2;     // 18432 B
    constexpr uint32_t KVPLANE = 64 * LDS * 2;      // 9216 B
    constexpr uint32_t STAGE_B = 4 * KVPLANE;       // 36864 B
    extern __shared__ __nv_bfloat16 sm[];
    const uint32_t qbase  = smem_u32(sm);
    const uint32_t kvbase = qbase + 2 * QPLANE;

    const int tid = threadIdx.x;
    const int wid = tid >> 5, lane = tid & 31;
    const int z = blockIdx.y, b = z / H_, hh = z % H_;
    const int row0 = blockIdx.x * 128;

    const __nv_bfloat16* qh = QKVhi + ((size_t)b * N_ + row0) * (3 * C_) + hh * D_;
    const __nv_bfloat16* ql = QKVlo + ((size_t)b * N_ + row0) * (3 * C_) + hh * D_;
    const __nv_bfloat16* kh = QKVhi + (size_t)b * N_ * (3 * C_) + C_ + hh * D_;
    const __nv_bfloat16* kl = QKVlo + (size_t)b * N_ * (3 * C_) + C_ + hh * D_;
    const __nv_bfloat16* vh = QKVhi + (size_t)b * N_ * (3 * C_) + 2 * C_ + hh * D_;
    const __nv_bfloat16* vl = QKVlo + (size_t)b * N_ * (3 * C_) + 2 * C_ + hh * D_;

    // Q copy (2 planes x 128 rows x 16 x 8B), grouped with KV chunk 0
#pragma unroll
    for (int i = 0; i < 16; i++) {
        const int u = i * 256 + tid;
        const int plane = u >> 11, r = (u >> 4) & 127, seg = u & 15;
        CP_ASYNC8(qbase + plane * QPLANE + (uint32_t)(r * 144 + seg * 8),
                  (plane ? ql : qh) + (size_t)r * (3 * C_) + seg * 4);
    }
    auto issueKV = [&](int c, int stage) {
        const int k0 = c * 64;
#pragma unroll
        for (int i = 0; i < 16; i++) {
            const int u = i * 256 + tid;
            const int plane = u >> 10, r = (u >> 4) & 63, seg = u & 15;
            const __nv_bfloat16* base =
                plane == 0 ? kh : plane == 1 ? kl : plane == 2 ? vh : vl;
            CP_ASYNC8(kvbase + stage * STAGE_B + plane * KVPLANE + (uint32_t)(r * 144 + seg * 8),
                      base + (size_t)(k0 + r) * (3 * C_) + seg * 4);
        }
    };
    issueKV(0, 0);
    CP_COMMIT();

    const int lar = lane & 15, lac = (lane >> 4) * 8;
    const int bq = lane >> 3, br = lane & 7;
    const int brow = (bq >> 1) * 8 + br, bcol = (bq & 1) * 8;

    uint32_t qf[2][4][4];
    float oacc[8][4] = {};
    float m_run0 = -1e30f, m_run1 = -1e30f;
    float l_run0 = 0.f, l_run1 = 0.f;

    for (int c = 0; c < 8; c++) {
        if (c + 1 < 8) issueKV(c + 1, (c + 1) & 1);
        CP_COMMIT();
        CP_WAIT1();
        __syncthreads();
        if (c == 0) {
#pragma unroll
            for (int pl = 0; pl < 2; pl++)
#pragma unroll
                for (int ks = 0; ks < 4; ks++)
                    LDSM_X4(qf[pl][ks][0], qf[pl][ks][1], qf[pl][ks][2], qf[pl][ks][3],
                            qbase + pl * QPLANE +
                            (uint32_t)(((wid * 16 + lar) * LDS + ks * 16 + lac) * 2));
        }
        const uint32_t st = kvbase + (c & 1) * STAGE_B;
        const uint32_t kHi = st, kLo = st + KVPLANE;
        const uint32_t vHi = st + 2 * KVPLANE, vLo = st + 3 * KVPLANE;

        // ---- S = Q @ K^T (16 x 64 per warp) ----
        float sacc[8][4] = {};
#pragma unroll
        for (int ks = 0; ks < 4; ks++) {
            uint32_t bh_[8][2], bl_[8][2];
#pragma unroll
            for (int nb = 0; nb < 4; nb++) {
                const uint32_t off = (uint32_t)(((nb * 16 + brow) * LDS + ks * 16 + bcol) * 2);
                LDSM_X4(bh_[2*nb][0], bh_[2*nb][1], bh_[2*nb+1][0], bh_[2*nb+1][1], kHi + off);
                LDSM_X4(bl_[2*nb][0], bl_[2*nb][1], bl_[2*nb+1][0], bl_[2*nb+1][1], kLo + off);
            }
#pragma unroll
            for (int nt = 0; nt < 8; nt++) {
                mma_bf16(sacc[nt], qf[0][ks], bh_[nt]);
                mma_bf16(sacc[nt], qf[0][ks], bl_[nt]);
                mma_bf16(sacc[nt], qf[1][ks], bh_[nt]);
            }
        }

        // ---- online softmax (rows: r = lane>>2 and r+8) ----
        float mc0 = -1e30f, mc1 = -1e30f;
#pragma unroll
        for (int nt = 0; nt < 8; nt++) {
            mc0 = fmaxf(mc0, fmaxf(sacc[nt][0], sacc[nt][1]));
            mc1 = fmaxf(mc1, fmaxf(sacc[nt][2], sacc[nt][3]));
        }
        mc0 *= 0.125f; mc1 *= 0.125f;
#pragma unroll
        for (int o = 1; o <= 2; o <<= 1) {
            mc0 = fmaxf(mc0, __shfl_xor_sync(0xffffffffu, mc0, o));
            mc1 = fmaxf(mc1, __shfl_xor_sync(0xffffffffu, mc1, o));
        }
        const float mn0 = fmaxf(m_run0, mc0), mn1 = fmaxf(m_run1, mc1);
        const float a0 = __expf(m_run0 - mn0), a1 = __expf(m_run1 - mn1);
        m_run0 = mn0; m_run1 = mn1;
        float lc0 = 0.f, lc1 = 0.f;
#pragma unroll
        for (int nt = 0; nt < 8; nt++) {
            sacc[nt][0] = __expf(sacc[nt][0] * 0.125f - mn0);
            sacc[nt][1] = __expf(sacc[nt][1] * 0.125f - mn0);
            sacc[nt][2] = __expf(sacc[nt][2] * 0.125f - mn1);
            sacc[nt][3] = __expf(sacc[nt][3] * 0.125f - mn1);
            lc0 += sacc[nt][0] + sacc[nt][1];
            lc1 += sacc[nt][2] + sacc[nt][3];
            oacc[nt][0] *= a0; oacc[nt][1] *= a0;
            oacc[nt][2] *= a1; oacc[nt][3] *= a1;
        }
        l_run0 = l_run0 * a0 + lc0;
        l_run1 = l_run1 * a1 + lc1;

        // ---- O += P @ V ----
#pragma unroll
        for (int ks = 0; ks < 4; ks++) {
            const int t0 = 2 * ks, t1 = t0 + 1;
            uint32_t ph[4], plo_[4];
            split_pair(sacc[t0][0], sacc[t0][1], ph[0], plo_[0]);
            split_pair(sacc[t0][2], sacc[t0][3], ph[1], plo_[1]);
            split_pair(sacc[t1][0], sacc[t1][1], ph[2], plo_[2]);
            split_pair(sacc[t1][2], sacc[t1][3], ph[3], plo_[3]);
            uint32_t vh_[8][2], vl_[8][2];
#pragma unroll
            for (int nb = 0; nb < 4; nb++) {
                const uint32_t off =
                    (uint32_t)(((ks * 16 + (bq & 1) * 8 + br) * LDS + nb * 16 + (bq >> 1) * 8) * 2);
                LDSM_X4_T(vh_[2*nb][0], vh_[2*nb][1], vh_[2*nb+1][0], vh_[2*nb+1][1], vHi + off);
                LDSM_X4_T(vl_[2*nb][0], vl_[2*nb][1], vl_[2*nb+1][0], vl_[2*nb+1][1], vLo + off);
            }
#pragma unroll
            for (int nt = 0; nt < 8; nt++) {
                mma_bf16(oacc[nt], ph, vh_[nt]);
                mma_bf16(oacc[nt], ph, vl_[nt]);
                mma_bf16(oacc[nt], plo_, vh_[nt]);
            }
        }
        __syncthreads();
    }

    // ---- finalize ----
#pragma unroll
    for (int o = 1; o <= 2; o <<= 1) {
        l_run0 += __shfl_xor_sync(0xffffffffu, l_run0, o);
        l_run1 += __shfl_xor_sync(0xffffffffu, l_run1, o);
    }
    const float inv0 = 1.f / l_run0, inv1 = 1.f / l_run1;
    const int rA = lane >> 2, colb = (lane & 3) * 2;
    const size_t obase = ((size_t)b * N_ + row0 + wid * 16) * C_ + hh * D_;
#pragma unroll
    for (int nt = 0; nt < 8; nt++) {
        split_store(Ohi, Olo, obase + (size_t)rA * C_ + nt * 8 + colb,
                    oacc[nt][0] * inv0, oacc[nt][1] * inv0);
        split_store(Ohi, Olo, obase + (size_t)(rA + 8) * C_ + nt * 8 + colb,
                    oacc[nt][2] * inv1, oacc[nt][3] * inv1);
    }
}

// ---------------------------------------------------------------------------
// bf16-split HMMA GEMM with cp.async 2-stage pipeline (unchanged from R5).
// EPI: 0 -> hi/lo planes; 2 -> 2*(v+bias) fp32; 3 -> gelu(v+bias) planes;
//      4 -> v+bias+res fp32
// ---------------------------------------------------------------------------
template <int EPI>
__global__ void __launch_bounds__(256) mma_gemm2(
    const __nv_bfloat16* __restrict__ Ahi, const __nv_bfloat16* __restrict__ Alo,
    const __nv_bfloat16* __restrict__ Bhi, const __nv_bfloat16* __restrict__ Blo,
    const float* __restrict__ bias, const float* __restrict__ res,
    float* __restrict__ Cf, __nv_bfloat16* __restrict__ Chi, __nv_bfloat16* __restrict__ Clo,
    int K, int lda, int ldb, int ldc)
{
    constexpr int LDS = 40;
    constexpr uint32_t PLANE_B = 128 * LDS * 2;   // 10240
    constexpr uint32_t STAGE_B = 4 * PLANE_B;     // 40960
    extern __shared__ __nv_bfloat16 sm[];
    const uint32_t sbase = smem_u32(sm);

    const int tid = threadIdx.x;
    const int wid = tid >> 5, lane = tid & 31;
    const int wm = wid & 1, wn = wid >> 1;
    const int mOff = wm * 64, nOff = wn * 32;

    const int row0 = blockIdx.y * 128, col0 = blockIdx.x * 128;
    const __nv_bfloat16* pl[4] = {
        Ahi + (size_t)row0 * lda, Alo + (size_t)row0 * lda,
        Bhi + (size_t)col0 * ldb, Blo + (size_t)col0 * ldb };

    const int lr = tid >> 3, lc4 = (tid & 7) * 4;

    auto issue = [&](int c, int stage) {
        const int k0 = c * 32;
        const uint32_t sst = sbase + stage * STAGE_B;
#pragma unroll
        for (int p = 0; p < 4; p++) {
            const __nv_bfloat16* base = pl[p];
            const int ld = (p < 2) ? lda : ldb;
            const uint32_t sp = sst + p * PLANE_B;
#pragma unroll
            for (int i = 0; i < 4; i++) {
                const int r = i * 32 + lr;
                CP_ASYNC8(sp + (uint32_t)(r * 80 + lc4 * 2),
                          base + (size_t)r * ld + k0 + lc4);
            }
        }
    };

    const int lar = lane & 15, lac = (lane >> 4) * 8;
    const int bq = lane >> 3, br = lane & 7;
    const int brow = (bq >> 1) * 8 + br, bcol = (bq & 1) * 8;

    float acc[4][4][4] = {};

    const int chunks = K / 32;
    issue(0, 0);
    CP_COMMIT();
    for (int c = 0; c < chunks; c++) {
        if (c + 1 < chunks) issue(c + 1, (c + 1) & 1);
        CP_COMMIT();
        CP_WAIT1();
        __syncthreads();
        const uint32_t sst = sbase + (c & 1) * STAGE_B;
        const uint32_t aHi = sst, aLo = sst + PLANE_B;
        const uint32_t bHi = sst + 2 * PLANE_B, bLo = sst + 3 * PLANE_B;
#pragma unroll
        for (int term = 0; term < 3; term++) {
            const uint32_t ab = (term == 2) ? aLo : aHi;
            const uint32_t bb = (term == 1) ? bLo : bHi;
#pragma unroll
            for (int kk = 0; kk < 32; kk += 16) {
                uint32_t af[4][4];
#pragma unroll
                for (int mi = 0; mi < 4; mi++)
                    LDSM_X4(af[mi][0], af[mi][1], af[mi][2], af[mi][3],
                            ab + (uint32_t)(((mOff + mi * 16 + lar) * LDS + kk + lac) * 2));
                uint32_t bf[4][2];
#pragma unroll
                for (int nb = 0; nb < 2; nb++)
                    LDSM_X4(bf[2 * nb][0], bf[2 * nb][1], bf[2 * nb + 1][0], bf[2 * nb + 1][1],
                            bb + (uint32_t)(((nOff + nb * 16 + brow) * LDS + kk + bcol) * 2));
#pragma unroll
                for (int mi = 0; mi < 4; mi++)
#pragma unroll
                    for (int ni = 0; ni < 4; ni++)
                        mma_bf16(acc[mi][ni], af[mi], bf[ni]);
            }
        }
        __syncthreads();
    }

#pragma unroll
    for (int mi = 0; mi < 4; mi++) {
#pragma unroll
        for (int ni = 0; ni < 4; ni++) {
#pragma unroll
            for (int h = 0; h < 2; h++) {
                const int r = row0 + mOff + mi * 16 + (lane >> 2) + h * 8;
                const int c = col0 + nOff + ni * 8 + (lane & 3) * 2;
                float v0 = acc[mi][ni][2 * h + 0];
                float v1 = acc[mi][ni][2 * h + 1];
                const size_t gi = (size_t)r * ldc + c;
                if (EPI == 0) {
                    split_store(Chi, Clo, gi, v0, v1);
                } else if (EPI == 2) {
                    *(float2*)(Cf + gi) = make_float2(2.f * (v0 + bias[c]), 2.f * (v1 + bias[c + 1]));
                } else if (EPI == 3) {
                    v0 += bias[c];  v1 += bias[c + 1];
                    v0 = 0.5f * v0 * (1.f + erff(v0 * 0.70710678118654752f));
                    v1 = 0.5f * v1 * (1.f + erff(v1 * 0.70710678118654752f));
                    split_store(Chi, Clo, gi, v0, v1);
                } else {  // EPI 4
                    v0 += bias[c] + res[gi];
                    v1 += bias[c + 1] + res[gi + 1];
                    *(float2*)(Cf + gi) = make_float2(v0, v1);
                }
            }
        }
    }
}

// ---------------------------------------------------------------------------
// Launch sequence
// ---------------------------------------------------------------------------
extern "C" void kernel_launch(void* const* d_in, const int* in_sizes, int n_in,
                              void* d_out, int out_size) {
    (void)in_sizes; (void)n_in; (void)out_size;
    const float* x      = (const float*)d_in[0];
    const float* ln1_w  = (const float*)d_in[1];
    const float* ln1_b  = (const float*)d_in[2];
    const float* qkv_w  = (const float*)d_in[3];
    const float* proj_w = (const float*)d_in[4];
    const float* proj_b = (const float*)d_in[5];
    const float* ln2_w  = (const float*)d_in[6];
    const float* ln2_b  = (const float*)d_in[7];
    const float* fc1_w  = (const float*)d_in[8];
    const float* fc1_b  = (const float*)d_in[9];
    const float* fc2_w  = (const float*)d_in[10];
    const float* fc2_b  = (const float*)d_in[11];
    float* out = (float*)d_out;

    float *xres;
    __nv_bfloat16 *h_hi, *h_lo, *qkv_hi, *qkv_lo, *o_hi, *o_lo, *f1_hi, *f1_lo;
    __nv_bfloat16 *qw_hi, *qw_lo, *pw_hi, *pw_lo, *f1w_hi, *f1w_lo, *f2w_hi, *f2w_lo;
    cudaGetSymbolAddress((void**)&xres,   g_xres);
    cudaGetSymbolAddress((void**)&h_hi,   g_h_hi);   cudaGetSymbolAddress((void**)&h_lo,   g_h_lo);
    cudaGetSymbolAddress((void**)&qkv_hi, g_qkv_hi); cudaGetSymbolAddress((void**)&qkv_lo, g_qkv_lo);
    cudaGetSymbolAddress((void**)&o_hi,   g_o_hi);   cudaGetSymbolAddress((void**)&o_lo,   g_o_lo);
    cudaGetSymbolAddress((void**)&f1_hi,  g_f1_hi);  cudaGetSymbolAddress((void**)&f1_lo,  g_f1_lo);
    cudaGetSymbolAddress((void**)&qw_hi,  g_qkvw_hi);  cudaGetSymbolAddress((void**)&qw_lo,  g_qkvw_lo);
    cudaGetSymbolAddress((void**)&pw_hi,  g_projw_hi); cudaGetSymbolAddress((void**)&pw_lo,  g_projw_lo);
    cudaGetSymbolAddress((void**)&f1w_hi, g_fc1w_hi);  cudaGetSymbolAddress((void**)&f1w_lo, g_fc1w_lo);
    cudaGetSymbolAddress((void**)&f2w_hi, g_fc2w_hi);  cudaGetSymbolAddress((void**)&f2w_lo, g_fc2w_lo);

    constexpr int SMEM_GEMM  = 2 * 4 * 128 * 40 * 2;                     // 81920
    constexpr int SMEM_FLASH = 2 * 128 * 72 * 2 + 2 * 4 * 64 * 72 * 2;   // 110592
    cudaFuncSetAttribute(mma_gemm2<0>, cudaFuncAttributeMaxDynamicSharedMemorySize, SMEM_GEMM);
    cudaFuncSetAttribute(mma_gemm2<2>, cudaFuncAttributeMaxDynamicSharedMemorySize, SMEM_GEMM);
    cudaFuncSetAttribute(mma_gemm2<3>, cudaFuncAttributeMaxDynamicSharedMemorySize, SMEM_GEMM);
    cudaFuncSetAttribute(mma_gemm2<4>, cudaFuncAttributeMaxDynamicSharedMemorySize, SMEM_GEMM);
    cudaFuncSetAttribute(flash_kernel, cudaFuncAttributeMaxDynamicSharedMemorySize, SMEM_FLASH);

    // 0. pre-split weights to bf16 hi/lo
    cvt_kernel<<<(3 * C_ * C_ / 4 + 255) / 256, 256>>>(qkv_w,  qw_hi,  qw_lo,  3 * C_ * C_ / 4);
    cvt_kernel<<<(C_ * C_ / 4 + 255) / 256, 256>>>(proj_w, pw_hi,  pw_lo,  C_ * C_ / 4);
    cvt_kernel<<<(HID_ * C_ / 4 + 255) / 256, 256>>>(fc1_w,  f1w_hi, f1w_lo, HID_ * C_ / 4);
    cvt_kernel<<<(C_ * HID_ / 4 + 255) / 256, 256>>>(fc2_w,  f2w_hi, f2w_lo, C_ * HID_ / 4);

    // 1. LN1 -> h planes
    ln_bf_kernel<<<M_, 256>>>(x, ln1_w, ln1_b, h_hi, h_lo);
    // 2. QKV -> qkv planes
    mma_gemm2<0><<<dim3(18, 128, 1), 256, SMEM_GEMM>>>(
        h_hi, h_lo, qw_hi, qw_lo, nullptr, nullptr, nullptr, qkv_hi, qkv_lo,
        C_, C_, C_, 3 * C_);
    // 3-5. flash attention -> o planes
    flash_kernel<<<dim3(4, BH_), 256, SMEM_FLASH>>>(qkv_hi, qkv_lo, o_hi, o_lo);
    // 6. xres = 2*(o @ proj_w^T + proj_b)
    mma_gemm2<2><<<dim3(6, 128, 1), 256, SMEM_GEMM>>>(
        o_hi, o_lo, pw_hi, pw_lo, proj_b, nullptr, xres, nullptr, nullptr,
        C_, C_, C_, C_);
    // 7. LN2 -> h planes
    ln_bf_kernel<<<M_, 256>>>(xres, ln2_w, ln2_b, h_hi, h_lo);
    // 8. fc1 + GELU -> f1 planes
    mma_gemm2<3><<<dim3(24, 128, 1), 256, SMEM_GEMM>>>(
        h_hi, h_lo, f1w_hi, f1w_lo, fc1_b, nullptr, nullptr, f1_hi, f1_lo,
        C_, C_, C_, HID_);
    // 9. out = xres + f1 @ fc2_w^T + fc2_b
    mma_gemm2<4><<<dim3(6, 128, 1), 256, SMEM_GEMM>>>(
        f1_hi, f1_lo, f2w_hi, f2w_lo, fc2_b, xres, out, nullptr, nullptr,
        HID_, HID_, HID_, C_);
}

// round 8
// speedup vs baseline: 3.2850x; 1.0973x over previous
#include <cuda_runtime.h>
#include <cuda_bf16.h>
#include <math.h>
#include <stdint.h>

namespace {
constexpr int B_   = 32;
constexpr int N_   = 512;
constexpr int C_   = 768;
constexpr int H_   = 12;
constexpr int D_   = 64;
constexpr int HID_ = 3072;
constexpr int M_   = B_ * N_;   // 16384
constexpr int BH_  = B_ * H_;   // 384
}

// fp32 scratch
__device__ float g_xres[M_ * C_];
// bf16 hi/lo planes
__device__ __nv_bfloat16 g_h_hi[M_ * C_],      g_h_lo[M_ * C_];
__device__ __nv_bfloat16 g_qkv_hi[M_ * 3 * C_],g_qkv_lo[M_ * 3 * C_];
__device__ __nv_bfloat16 g_o_hi[M_ * C_],      g_o_lo[M_ * C_];
__device__ __nv_bfloat16 g_f1_hi[M_ * HID_],   g_f1_lo[M_ * HID_];
__device__ __nv_bfloat16 g_qkvw_hi[3 * C_ * C_], g_qkvw_lo[3 * C_ * C_];
__device__ __nv_bfloat16 g_projw_hi[C_ * C_],  g_projw_lo[C_ * C_];
__device__ __nv_bfloat16 g_fc1w_hi[HID_ * C_], g_fc1w_lo[HID_ * C_];
__device__ __nv_bfloat16 g_fc2w_hi[C_ * HID_], g_fc2w_lo[C_ * HID_];

// ---------------------------------------------------------------------------
// helpers
// ---------------------------------------------------------------------------
__device__ __forceinline__ uint32_t smem_u32(const void* p) {
    uint32_t a;
    asm("{ .reg .u64 t; cvta.to.shared.u64 t, %1; cvt.u32.u64 %0, t; }" : "=r"(a) : "l"(p));
    return a;
}
#define CP_ASYNC8(dst, src) \
    asm volatile("cp.async.ca.shared.global [%0], [%1], 8;" :: "r"(dst), "l"(src))
#define CP_COMMIT() asm volatile("cp.async.commit_group;" ::: "memory")
#define CP_WAIT1()  asm volatile("cp.async.wait_group 1;" ::: "memory")

#define LDSM_X4(r0, r1, r2, r3, addr)                                             \
    asm volatile("ldmatrix.sync.aligned.m8n8.x4.shared.b16 {%0,%1,%2,%3}, [%4];"  \
                 : "=r"(r0), "=r"(r1), "=r"(r2), "=r"(r3) : "r"(addr))
#define LDSM_X4_T(r0, r1, r2, r3, addr)                                                \
    asm volatile("ldmatrix.sync.aligned.m8n8.x4.trans.shared.b16 {%0,%1,%2,%3}, [%4];" \
                 : "=r"(r0), "=r"(r1), "=r"(r2), "=r"(r3) : "r"(addr))
__device__ __forceinline__ void mma_bf16(float* c, const uint32_t* a, const uint32_t* b) {
    asm volatile(
        "mma.sync.aligned.m16n8k16.row.col.f32.bf16.bf16.f32 "
        "{%0,%1,%2,%3}, {%4,%5,%6,%7}, {%8,%9}, {%0,%1,%2,%3};"
        : "+f"(c[0]), "+f"(c[1]), "+f"(c[2]), "+f"(c[3])
        : "r"(a[0]), "r"(a[1]), "r"(a[2]), "r"(a[3]), "r"(b[0]), "r"(b[1]));
}
__device__ __forceinline__ uint32_t pack2(float x, float y) {
    __nv_bfloat162 t = __floats2bfloat162_rn(x, y);
    return *reinterpret_cast<uint32_t*>(&t);
}
__device__ __forceinline__ void split_pair(float x, float y, uint32_t& hi, uint32_t& lo) {
    const __nv_bfloat16 hx = __float2bfloat16_rn(x);
    const __nv_bfloat16 hy = __float2bfloat16_rn(y);
    __nv_bfloat162 hp; hp.x = hx; hp.y = hy;
    hi = *reinterpret_cast<uint32_t*>(&hp);
    lo = pack2(x - __bfloat162float(hx), y - __bfloat162float(hy));
}
__device__ __forceinline__ void split_store(__nv_bfloat16* hi, __nv_bfloat16* lo,
                                            size_t gi, float v0, float v1) {
    uint32_t h, l;
    split_pair(v0, v1, h, l);
    *(uint32_t*)(hi + gi) = h;
    *(uint32_t*)(lo + gi) = l;
}

// ---------------------------------------------------------------------------
// weight convert: fp32 -> bf16 hi/lo planes
// ---------------------------------------------------------------------------
__global__ void cvt_kernel(const float* __restrict__ src, __nv_bfloat16* __restrict__ hi,
                           __nv_bfloat16* __restrict__ lo, int n4) {
    const int i = blockIdx.x * 256 + threadIdx.x;
    if (i >= n4) return;
    const float4 v = ((const float4*)src)[i];
    split_store(hi, lo, (size_t)i * 4, v.x, v.y);
    split_store(hi, lo, (size_t)i * 4 + 2, v.z, v.w);
}

// ---------------------------------------------------------------------------
// LayerNorm -> bf16 hi/lo planes
// ---------------------------------------------------------------------------
__global__ void ln_bf_kernel(const float* __restrict__ x, const float* __restrict__ w,
                             const float* __restrict__ bia,
                             __nv_bfloat16* __restrict__ hi, __nv_bfloat16* __restrict__ lo) {
    __shared__ float red[256];
    const int row = blockIdx.x;
    const int t = threadIdx.x;
    const float* xr = x + (size_t)row * C_;
    float v[3];
    float s = 0.f, s2 = 0.f;
#pragma unroll
    for (int j = 0; j < 3; j++) { v[j] = xr[t + 256 * j]; s += v[j]; s2 += v[j] * v[j]; }
    red[t] = s; __syncthreads();
    for (int o = 128; o > 0; o >>= 1) { if (t < o) red[t] += red[t + o]; __syncthreads(); }
    const float mean = red[0] * (1.f / C_);
    __syncthreads();
    red[t] = s2; __syncthreads();
    for (int o = 128; o > 0; o >>= 1) { if (t < o) red[t] += red[t + o]; __syncthreads(); }
    const float var = red[0] * (1.f / C_) - mean * mean;
    const float rstd = rsqrtf(var + 1e-5f);
#pragma unroll
    for (int j = 0; j < 3; j++) {
        const int c = t + 256 * j;
        const float y = (v[j] - mean) * rstd * w[c] + bia[c];
        const size_t gi = (size_t)row * C_ + c;
        const __nv_bfloat16 h = __float2bfloat16_rn(y);
        hi[gi] = h;
        lo[gi] = __float2bfloat16_rn(y - __bfloat162float(h));
    }
}

// ---------------------------------------------------------------------------
// Flash attention (validated in R6, unchanged)
// ---------------------------------------------------------------------------
__global__ void __launch_bounds__(256) flash_kernel(
    const __nv_bfloat16* __restrict__ QKVhi, const __nv_bfloat16* __restrict__ QKVlo,
    __nv_bfloat16* __restrict__ Ohi, __nv_bfloat16* __restrict__ Olo)
{
    constexpr int LDS = 72;
    constexpr uint32_t QPLANE  = 128 * LDS * 2;
    constexpr uint32_t KVPLANE = 64 * LDS * 2;
    constexpr uint32_t STAGE_B = 4 * KVPLANE;
    extern __shared__ __nv_bfloat16 sm[];
    const uint32_t qbase  = smem_u32(sm);
    const uint32_t kvbase = qbase + 2 * QPLANE;

    const int tid = threadIdx.x;
    const int wid = tid >> 5, lane = tid & 31;
    const int z = blockIdx.y, b = z / H_, hh = z % H_;
    const int row0 = blockIdx.x * 128;

    const __nv_bfloat16* qh = QKVhi + ((size_t)b * N_ + row0) * (3 * C_) + hh * D_;
    const __nv_bfloat16* ql = QKVlo + ((size_t)b * N_ + row0) * (3 * C_) + hh * D_;
    const __nv_bfloat16* kh = QKVhi + (size_t)b * N_ * (3 * C_) + C_ + hh * D_;
    const __nv_bfloat16* kl = QKVlo + (size_t)b * N_ * (3 * C_) + C_ + hh * D_;
    const __nv_bfloat16* vh = QKVhi + (size_t)b * N_ * (3 * C_) + 2 * C_ + hh * D_;
    const __nv_bfloat16* vl = QKVlo + (size_t)b * N_ * (3 * C_) + 2 * C_ + hh * D_;

#pragma unroll
    for (int i = 0; i < 16; i++) {
        const int u = i * 256 + tid;
        const int plane = u >> 11, r = (u >> 4) & 127, seg = u & 15;
        CP_ASYNC8(qbase + plane * QPLANE + (uint32_t)(r * 144 + seg * 8),
                  (plane ? ql : qh) + (size_t)r * (3 * C_) + seg * 4);
    }
    auto issueKV = [&](int c, int stage) {
        const int k0 = c * 64;
#pragma unroll
        for (int i = 0; i < 16; i++) {
            const int u = i * 256 + tid;
            const int plane = u >> 10, r = (u >> 4) & 63, seg = u & 15;
            const __nv_bfloat16* base =
                plane == 0 ? kh : plane == 1 ? kl : plane == 2 ? vh : vl;
            CP_ASYNC8(kvbase + stage * STAGE_B + plane * KVPLANE + (uint32_t)(r * 144 + seg * 8),
                      base + (size_t)(k0 + r) * (3 * C_) + seg * 4);
        }
    };
    issueKV(0, 0);
    CP_COMMIT();

    const int lar = lane & 15, lac = (lane >> 4) * 8;
    const int bq = lane >> 3, br = lane & 7;
    const int brow = (bq >> 1) * 8 + br, bcol = (bq & 1) * 8;

    uint32_t qf[2][4][4];
    float oacc[8][4] = {};
    float m_run0 = -1e30f, m_run1 = -1e30f;
    float l_run0 = 0.f, l_run1 = 0.f;

    for (int c = 0; c < 8; c++) {
        if (c + 1 < 8) issueKV(c + 1, (c + 1) & 1);
        CP_COMMIT();
        CP_WAIT1();
        __syncthreads();
        if (c == 0) {
#pragma unroll
            for (int pl = 0; pl < 2; pl++)
#pragma unroll
                for (int ks = 0; ks < 4; ks++)
                    LDSM_X4(qf[pl][ks][0], qf[pl][ks][1], qf[pl][ks][2], qf[pl][ks][3],
                            qbase + pl * QPLANE +
                            (uint32_t)(((wid * 16 + lar) * LDS + ks * 16 + lac) * 2));
        }
        const uint32_t st = kvbase + (c & 1) * STAGE_B;
        const uint32_t kHi = st, kLo = st + KVPLANE;
        const uint32_t vHi = st + 2 * KVPLANE, vLo = st + 3 * KVPLANE;

        float sacc[8][4] = {};
#pragma unroll
        for (int ks = 0; ks < 4; ks++) {
            uint32_t bh_[8][2], bl_[8][2];
#pragma unroll
            for (int nb = 0; nb < 4; nb++) {
                const uint32_t off = (uint32_t)(((nb * 16 + brow) * LDS + ks * 16 + bcol) * 2);
                LDSM_X4(bh_[2*nb][0], bh_[2*nb][1], bh_[2*nb+1][0], bh_[2*nb+1][1], kHi + off);
                LDSM_X4(bl_[2*nb][0], bl_[2*nb][1], bl_[2*nb+1][0], bl_[2*nb+1][1], kLo + off);
            }
#pragma unroll
            for (int nt = 0; nt < 8; nt++) {
                mma_bf16(sacc[nt], qf[0][ks], bh_[nt]);
                mma_bf16(sacc[nt], qf[0][ks], bl_[nt]);
                mma_bf16(sacc[nt], qf[1][ks], bh_[nt]);
            }
        }

        float mc0 = -1e30f, mc1 = -1e30f;
#pragma unroll
        for (int nt = 0; nt < 8; nt++) {
            mc0 = fmaxf(mc0, fmaxf(sacc[nt][0], sacc[nt][1]));
            mc1 = fmaxf(mc1, fmaxf(sacc[nt][2], sacc[nt][3]));
        }
        mc0 *= 0.125f; mc1 *= 0.125f;
#pragma unroll
        for (int o = 1; o <= 2; o <<= 1) {
            mc0 = fmaxf(mc0, __shfl_xor_sync(0xffffffffu, mc0, o));
            mc1 = fmaxf(mc1, __shfl_xor_sync(0xffffffffu, mc1, o));
        }
        const float mn0 = fmaxf(m_run0, mc0), mn1 = fmaxf(m_run1, mc1);
        const float a0 = __expf(m_run0 - mn0), a1 = __expf(m_run1 - mn1);
        m_run0 = mn0; m_run1 = mn1;
        float lc0 = 0.f, lc1 = 0.f;
#pragma unroll
        for (int nt = 0; nt < 8; nt++) {
            sacc[nt][0] = __expf(sacc[nt][0] * 0.125f - mn0);
            sacc[nt][1] = __expf(sacc[nt][1] * 0.125f - mn0);
            sacc[nt][2] = __expf(sacc[nt][2] * 0.125f - mn1);
            sacc[nt][3] = __expf(sacc[nt][3] * 0.125f - mn1);
            lc0 += sacc[nt][0] + sacc[nt][1];
            lc1 += sacc[nt][2] + sacc[nt][3];
            oacc[nt][0] *= a0; oacc[nt][1] *= a0;
            oacc[nt][2] *= a1; oacc[nt][3] *= a1;
        }
        l_run0 = l_run0 * a0 + lc0;
        l_run1 = l_run1 * a1 + lc1;

#pragma unroll
        for (int ks = 0; ks < 4; ks++) {
            const int t0 = 2 * ks, t1 = t0 + 1;
            uint32_t ph[4], plo_[4];
            split_pair(sacc[t0][0], sacc[t0][1], ph[0], plo_[0]);
            split_pair(sacc[t0][2], sacc[t0][3], ph[1], plo_[1]);
            split_pair(sacc[t1][0], sacc[t1][1], ph[2], plo_[2]);
            split_pair(sacc[t1][2], sacc[t1][3], ph[3], plo_[3]);
            uint32_t vh_[8][2], vl_[8][2];
#pragma unroll
            for (int nb = 0; nb < 4; nb++) {
                const uint32_t off =
                    (uint32_t)(((ks * 16 + (bq & 1) * 8 + br) * LDS + nb * 16 + (bq >> 1) * 8) * 2);
                LDSM_X4_T(vh_[2*nb][0], vh_[2*nb][1], vh_[2*nb+1][0], vh_[2*nb+1][1], vHi + off);
                LDSM_X4_T(vl_[2*nb][0], vl_[2*nb][1], vl_[2*nb+1][0], vl_[2*nb+1][1], vLo + off);
            }
#pragma unroll
            for (int nt = 0; nt < 8; nt++) {
                mma_bf16(oacc[nt], ph, vh_[nt]);
                mma_bf16(oacc[nt], ph, vl_[nt]);
                mma_bf16(oacc[nt], plo_, vh_[nt]);
            }
        }
        __syncthreads();
    }

#pragma unroll
    for (int o = 1; o <= 2; o <<= 1) {
        l_run0 += __shfl_xor_sync(0xffffffffu, l_run0, o);
        l_run1 += __shfl_xor_sync(0xffffffffu, l_run1, o);
    }
    const float inv0 = 1.f / l_run0, inv1 = 1.f / l_run1;
    const int rA = lane >> 2, colb = (lane & 3) * 2;
    const size_t obase = ((size_t)b * N_ + row0 + wid * 16) * C_ + hh * D_;
#pragma unroll
    for (int nt = 0; nt < 8; nt++) {
        split_store(Ohi, Olo, obase + (size_t)rA * C_ + nt * 8 + colb,
                    oacc[nt][0] * inv0, oacc[nt][1] * inv0);
        split_store(Ohi, Olo, obase + (size_t)(rA + 8) * C_ + nt * 8 + colb,
                    oacc[nt][2] * inv1, oacc[nt][3] * inv1);
    }
}

// ---------------------------------------------------------------------------
// bf16-split HMMA GEMM v3: block 128x256, warp tile 64x64, BK=32,
// fragment caching across the 3 split terms, 3-stage cp.async, 1 sync/chunk.
// EPI: 0 -> hi/lo planes; 2 -> 2*(v+bias) fp32; 3 -> gelu(v+bias) planes;
//      4 -> v+bias+res fp32
// ---------------------------------------------------------------------------
template <int EPI>
__global__ void __launch_bounds__(256) mma_gemm3(
    const __nv_bfloat16* __restrict__ Ahi, const __nv_bfloat16* __restrict__ Alo,
    const __nv_bfloat16* __restrict__ Bhi, const __nv_bfloat16* __restrict__ Blo,
    const float* __restrict__ bias, const float* __restrict__ res,
    float* __restrict__ Cf, __nv_bfloat16* __restrict__ Chi, __nv_bfloat16* __restrict__ Clo,
    int K, int lda, int ldb, int ldc)
{
    constexpr int LDS = 40;
    constexpr uint32_t APLANE = 128 * LDS * 2;               // 10240
    constexpr uint32_t BPLANE = 256 * LDS * 2;               // 20480
    constexpr uint32_t STAGE_B = 2 * APLANE + 2 * BPLANE;    // 61440
    extern __shared__ __nv_bfloat16 sm[];
    const uint32_t sbase = smem_u32(sm);

    const int tid = threadIdx.x;
    const int wid = tid >> 5, lane = tid & 31;
    const int mOff = (wid & 1) * 64, nOff = (wid >> 1) * 64;

    const int row0 = blockIdx.y * 128, col0 = blockIdx.x * 256;
    const __nv_bfloat16* Ah = Ahi + (size_t)row0 * lda;
    const __nv_bfloat16* Al = Alo + (size_t)row0 * lda;
    const __nv_bfloat16* Bh = Bhi + (size_t)col0 * ldb;
    const __nv_bfloat16* Bl = Blo + (size_t)col0 * ldb;

    auto issue = [&](int c, int stage) {
        const int k0 = c * 32;
        const uint32_t sst = sbase + stage * STAGE_B;
        // A planes: 2 x 128 rows x 8 segs of 8B (BK=32 -> 64B per row)
#pragma unroll
        for (int i = 0; i < 8; i++) {
            const int u = i * 256 + tid;
            const int plane = u >> 10, r = (u >> 3) & 127, seg = u & 7;
            CP_ASYNC8(sst + plane * APLANE + (uint32_t)(r * 80 + seg * 8),
                      (plane ? Al : Ah) + (size_t)r * lda + k0 + seg * 4);
        }
        // B planes: 2 x 256 rows x 8 segs
#pragma unroll
        for (int i = 0; i < 16; i++) {
            const int u = i * 256 + tid;
            const int plane = u >> 11, r = (u >> 3) & 255, seg = u & 7;
            CP_ASYNC8(sst + 2 * APLANE + plane * BPLANE + (uint32_t)(r * 80 + seg * 8),
                      (plane ? Bl : Bh) + (size_t)r * ldb + k0 + seg * 4);
        }
    };

    const int lar = lane & 15, lac = (lane >> 4) * 8;
    const int bq = lane >> 3, br = lane & 7;
    const int brow = (bq >> 1) * 8 + br, bcol = (bq & 1) * 8;

    float acc[4][8][4] = {};

    const int chunks = K / 32;
    issue(0, 0);
    CP_COMMIT();
    for (int c = 0; c < chunks; c++) {
        if (c + 1 < chunks) issue(c + 1, (c + 1) % 3);
        CP_COMMIT();
        CP_WAIT1();
        __syncthreads();
        const uint32_t sst = sbase + (c % 3) * STAGE_B;
        const uint32_t aHiB = sst, aLoB = sst + APLANE;
        const uint32_t bHiB = sst + 2 * APLANE, bLoB = sst + 2 * APLANE + BPLANE;
#pragma unroll
        for (int kk = 0; kk < 32; kk += 16) {
            uint32_t ah[4][4], bh_[8][2];
#pragma unroll
            for (int mi = 0; mi < 4; mi++)
                LDSM_X4(ah[mi][0], ah[mi][1], ah[mi][2], ah[mi][3],
                        aHiB + (uint32_t)(((mOff + mi * 16 + lar) * LDS + kk + lac) * 2));
#pragma unroll
            for (int nb = 0; nb < 4; nb++)
                LDSM_X4(bh_[2*nb][0], bh_[2*nb][1], bh_[2*nb+1][0], bh_[2*nb+1][1],
                        bHiB + (uint32_t)(((nOff + nb * 16 + brow) * LDS + kk + bcol) * 2));
            // term hh
#pragma unroll
            for (int mi = 0; mi < 4; mi++)
#pragma unroll
                for (int ni = 0; ni < 8; ni++)
                    mma_bf16(acc[mi][ni], ah[mi], bh_[ni]);
            // term hl: aHi x bLo
            {
                uint32_t bl_[8][2];
#pragma unroll
                for (int nb = 0; nb < 4; nb++)
                    LDSM_X4(bl_[2*nb][0], bl_[2*nb][1], bl_[2*nb+1][0], bl_[2*nb+1][1],
                            bLoB + (uint32_t)(((nOff + nb * 16 + brow) * LDS + kk + bcol) * 2));
#pragma unroll
                for (int mi = 0; mi < 4; mi++)
#pragma unroll
                    for (int ni = 0; ni < 8; ni++)
                        mma_bf16(acc[mi][ni], ah[mi], bl_[ni]);
            }
            // term lh: aLo x bHi
            {
                uint32_t al[4][4];
#pragma unroll
                for (int mi = 0; mi < 4; mi++)
                    LDSM_X4(al[mi][0], al[mi][1], al[mi][2], al[mi][3],
                            aLoB + (uint32_t)(((mOff + mi * 16 + lar) * LDS + kk + lac) * 2));
#pragma unroll
                for (int mi = 0; mi < 4; mi++)
#pragma unroll
                    for (int ni = 0; ni < 8; ni++)
                        mma_bf16(acc[mi][ni], al[mi], bh_[ni]);
            }
        }
    }

    // epilogue
#pragma unroll
    for (int mi = 0; mi < 4; mi++) {
#pragma unroll
        for (int ni = 0; ni < 8; ni++) {
#pragma unroll
            for (int h = 0; h < 2; h++) {
                const int r = row0 + mOff + mi * 16 + (lane >> 2) + h * 8;
                const int c = col0 + nOff + ni * 8 + (lane & 3) * 2;
                float v0 = acc[mi][ni][2 * h + 0];
                float v1 = acc[mi][ni][2 * h + 1];
                const size_t gi = (size_t)r * ldc + c;
                if (EPI == 0) {
                    split_store(Chi, Clo, gi, v0, v1);
                } else if (EPI == 2) {
                    *(float2*)(Cf + gi) = make_float2(2.f * (v0 + bias[c]), 2.f * (v1 + bias[c + 1]));
                } else if (EPI == 3) {
                    v0 += bias[c];  v1 += bias[c + 1];
                    v0 = 0.5f * v0 * (1.f + erff(v0 * 0.70710678118654752f));
                    v1 = 0.5f * v1 * (1.f + erff(v1 * 0.70710678118654752f));
                    split_store(Chi, Clo, gi, v0, v1);
                } else {  // EPI 4
                    v0 += bias[c] + res[gi];
                    v1 += bias[c + 1] + res[gi + 1];
                    *(float2*)(Cf + gi) = make_float2(v0, v1);
                }
            }
        }
    }
}

// ---------------------------------------------------------------------------
// Launch sequence
// ---------------------------------------------------------------------------
extern "C" void kernel_launch(void* const* d_in, const int* in_sizes, int n_in,
                              void* d_out, int out_size) {
    (void)in_sizes; (void)n_in; (void)out_size;
    const float* x      = (const float*)d_in[0];
    const float* ln1_w  = (const float*)d_in[1];
    const float* ln1_b  = (const float*)d_in[2];
    const float* qkv_w  = (const float*)d_in[3];
    const float* proj_w = (const float*)d_in[4];
    const float* proj_b = (const float*)d_in[5];
    const float* ln2_w  = (const float*)d_in[6];
    const float* ln2_b  = (const float*)d_in[7];
    const float* fc1_w  = (const float*)d_in[8];
    const float* fc1_b  = (const float*)d_in[9];
    const float* fc2_w  = (const float*)d_in[10];
    const float* fc2_b  = (const float*)d_in[11];
    float* out = (float*)d_out;

    float *xres;
    __nv_bfloat16 *h_hi, *h_lo, *qkv_hi, *qkv_lo, *o_hi, *o_lo, *f1_hi, *f1_lo;
    __nv_bfloat16 *qw_hi, *qw_lo, *pw_hi, *pw_lo, *f1w_hi, *f1w_lo, *f2w_hi, *f2w_lo;
    cudaGetSymbolAddress((void**)&xres,   g_xres);
    cudaGetSymbolAddress((void**)&h_hi,   g_h_hi);   cudaGetSymbolAddress((void**)&h_lo,   g_h_lo);
    cudaGetSymbolAddress((void**)&qkv_hi, g_qkv_hi); cudaGetSymbolAddress((void**)&qkv_lo, g_qkv_lo);
    cudaGetSymbolAddress((void**)&o_hi,   g_o_hi);   cudaGetSymbolAddress((void**)&o_lo,   g_o_lo);
    cudaGetSymbolAddress((void**)&f1_hi,  g_f1_hi);  cudaGetSymbolAddress((void**)&f1_lo,  g_f1_lo);
    cudaGetSymbolAddress((void**)&qw_hi,  g_qkvw_hi);  cudaGetSymbolAddress((void**)&qw_lo,  g_qkvw_lo);
    cudaGetSymbolAddress((void**)&pw_hi,  g_projw_hi); cudaGetSymbolAddress((void**)&pw_lo,  g_projw_lo);
    cudaGetSymbolAddress((void**)&f1w_hi, g_fc1w_hi);  cudaGetSymbolAddress((void**)&f1w_lo, g_fc1w_lo);
    cudaGetSymbolAddress((void**)&f2w_hi, g_fc2w_hi);  cudaGetSymbolAddress((void**)&f2w_lo, g_fc2w_lo);

    constexpr int SMEM_GEMM  = 3 * (2 * 128 * 40 + 2 * 256 * 40) * 2;    // 184320
    constexpr int SMEM_FLASH = 2 * 128 * 72 * 2 + 2 * 4 * 64 * 72 * 2;   // 110592
    cudaFuncSetAttribute(mma_gemm3<0>, cudaFuncAttributeMaxDynamicSharedMemorySize, SMEM_GEMM);
    cudaFuncSetAttribute(mma_gemm3<2>, cudaFuncAttributeMaxDynamicSharedMemorySize, SMEM_GEMM);
    cudaFuncSetAttribute(mma_gemm3<3>, cudaFuncAttributeMaxDynamicSharedMemorySize, SMEM_GEMM);
    cudaFuncSetAttribute(mma_gemm3<4>, cudaFuncAttributeMaxDynamicSharedMemorySize, SMEM_GEMM);
    cudaFuncSetAttribute(flash_kernel, cudaFuncAttributeMaxDynamicSharedMemorySize, SMEM_FLASH);

    // 0. pre-split weights to bf16 hi/lo
    cvt_kernel<<<(3 * C_ * C_ / 4 + 255) / 256, 256>>>(qkv_w,  qw_hi,  qw_lo,  3 * C_ * C_ / 4);
    cvt_kernel<<<(C_ * C_ / 4 + 255) / 256, 256>>>(proj_w, pw_hi,  pw_lo,  C_ * C_ / 4);
    cvt_kernel<<<(HID_ * C_ / 4 + 255) / 256, 256>>>(fc1_w,  f1w_hi, f1w_lo, HID_ * C_ / 4);
    cvt_kernel<<<(C_ * HID_ / 4 + 255) / 256, 256>>>(fc2_w,  f2w_hi, f2w_lo, C_ * HID_ / 4);

    // 1. LN1 -> h planes
    ln_bf_kernel<<<M_, 256>>>(x, ln1_w, ln1_b, h_hi, h_lo);
    // 2. QKV -> qkv planes
    mma_gemm3<0><<<dim3(9, 128, 1), 256, SMEM_GEMM>>>(
        h_hi, h_lo, qw_hi, qw_lo, nullptr, nullptr, nullptr, qkv_hi, qkv_lo,
        C_, C_, C_, 3 * C_);
    // 3-5. flash attention -> o planes
    flash_kernel<<<dim3(4, BH_), 256, SMEM_FLASH>>>(qkv_hi, qkv_lo, o_hi, o_lo);
    // 6. xres = 2*(o @ proj_w^T + proj_b)
    mma_gemm3<2><<<dim3(3, 128, 1), 256, SMEM_GEMM>>>(
        o_hi, o_lo, pw_hi, pw_lo, proj_b, nullptr, xres, nullptr, nullptr,
        C_, C_, C_, C_);
    // 7. LN2 -> h planes
    ln_bf_kernel<<<M_, 256>>>(xres, ln2_w, ln2_b, h_hi, h_lo);
    // 8. fc1 + GELU -> f1 planes
    mma_gemm3<3><<<dim3(12, 128, 1), 256, SMEM_GEMM>>>(
        h_hi, h_lo, f1w_hi, f1w_lo, fc1_b, nullptr, nullptr, f1_hi, f1_lo,
        C_, C_, C_, HID_);
    // 9. out = xres + f1 @ fc2_w^T + fc2_b
    mma_gemm3<4><<<dim3(3, 128, 1), 256, SMEM_GEMM>>>(
        f1_hi, f1_lo, f2w_hi, f2w_lo, fc2_b, xres, out, nullptr, nullptr,
        HID_, HID_, HID_, C_);
}

// round 12
// speedup vs baseline: 3.5228x; 1.0724x over previous
#include <cuda_runtime.h>
#include <cuda_bf16.h>
#include <math.h>
#include <stdint.h>

namespace {
constexpr int B_   = 32;
constexpr int N_   = 512;
constexpr int C_   = 768;
constexpr int H_   = 12;
constexpr int D_   = 64;
constexpr int HID_ = 3072;
constexpr int M_   = B_ * N_;   // 16384
constexpr int BH_  = B_ * H_;   // 384
}

// fp32 scratch
__device__ float g_xres[M_ * C_];
// bf16 hi/lo planes
__device__ __nv_bfloat16 g_h_hi[M_ * C_],      g_h_lo[M_ * C_];
__device__ __nv_bfloat16 g_qkv_hi[M_ * 3 * C_],g_qkv_lo[M_ * 3 * C_];
__device__ __nv_bfloat16 g_o_hi[M_ * C_],      g_o_lo[M_ * C_];
__device__ __nv_bfloat16 g_f1_hi[M_ * HID_],   g_f1_lo[M_ * HID_];
__device__ __nv_bfloat16 g_qkvw_hi[3 * C_ * C_], g_qkvw_lo[3 * C_ * C_];
__device__ __nv_bfloat16 g_projw_hi[C_ * C_],  g_projw_lo[C_ * C_];
__device__ __nv_bfloat16 g_fc1w_hi[HID_ * C_], g_fc1w_lo[HID_ * C_];
__device__ __nv_bfloat16 g_fc2w_hi[C_ * HID_], g_fc2w_lo[C_ * HID_];

// ---------------------------------------------------------------------------
// helpers
// ---------------------------------------------------------------------------
__device__ __forceinline__ uint32_t smem_u32(const void* p) {
    uint32_t a;
    asm("{ .reg .u64 t; cvta.to.shared.u64 t, %1; cvt.u32.u64 %0, t; }" : "=r"(a) : "l"(p));
    return a;
}
#define CP_ASYNC8(dst, src) \
    asm volatile("cp.async.ca.shared.global [%0], [%1], 8;" :: "r"(dst), "l"(src))
#define CP_ASYNC16(dst, src) \
    asm volatile("cp.async.cg.shared.global [%0], [%1], 16;" :: "r"(dst), "l"(src))
#define CP_COMMIT() asm volatile("cp.async.commit_group;" ::: "memory")
#define CP_WAIT1()  asm volatile("cp.async.wait_group 1;" ::: "memory")

#define LDSM_X4(r0, r1, r2, r3, addr)                                             \
    asm volatile("ldmatrix.sync.aligned.m8n8.x4.shared.b16 {%0,%1,%2,%3}, [%4];"  \
                 : "=r"(r0), "=r"(r1), "=r"(r2), "=r"(r3) : "r"(addr))
#define LDSM_X4_T(r0, r1, r2, r3, addr)                                                \
    asm volatile("ldmatrix.sync.aligned.m8n8.x4.trans.shared.b16 {%0,%1,%2,%3}, [%4];" \
                 : "=r"(r0), "=r"(r1), "=r"(r2), "=r"(r3) : "r"(addr))
__device__ __forceinline__ void mma_bf16(float* c, const uint32_t* a, const uint32_t* b) {
    asm volatile(
        "mma.sync.aligned.m16n8k16.row.col.f32.bf16.bf16.f32 "
        "{%0,%1,%2,%3}, {%4,%5,%6,%7}, {%8,%9}, {%0,%1,%2,%3};"
        : "+f"(c[0]), "+f"(c[1]), "+f"(c[2]), "+f"(c[3])
        : "r"(a[0]), "r"(a[1]), "r"(a[2]), "r"(a[3]), "r"(b[0]), "r"(b[1]));
}
__device__ __forceinline__ uint32_t pack2(float x, float y) {
    __nv_bfloat162 t = __floats2bfloat162_rn(x, y);
    return *reinterpret_cast<uint32_t*>(&t);
}
__device__ __forceinline__ void split_pair(float x, float y, uint32_t& hi, uint32_t& lo) {
    const __nv_bfloat16 hx = __float2bfloat16_rn(x);
    const __nv_bfloat16 hy = __float2bfloat16_rn(y);
    __nv_bfloat162 hp; hp.x = hx; hp.y = hy;
    hi = *reinterpret_cast<uint32_t*>(&hp);
    lo = pack2(x - __bfloat162float(hx), y - __bfloat162float(hy));
}
__device__ __forceinline__ void split_store(__nv_bfloat16* hi, __nv_bfloat16* lo,
                                            size_t gi, float v0, float v1) {
    uint32_t h, l;
    split_pair(v0, v1, h, l);
    *(uint32_t*)(hi + gi) = h;
    *(uint32_t*)(lo + gi) = l;
}

// ---------------------------------------------------------------------------
// weight convert: fp32 -> bf16 hi/lo planes
// ---------------------------------------------------------------------------
__global__ void cvt_kernel(const float* __restrict__ src, __nv_bfloat16* __restrict__ hi,
                           __nv_bfloat16* __restrict__ lo, int n4) {
    const int i = blockIdx.x * 256 + threadIdx.x;
    if (i >= n4) return;
    const float4 v = ((const float4*)src)[i];
    split_store(hi, lo, (size_t)i * 4, v.x, v.y);
    split_store(hi, lo, (size_t)i * 4 + 2, v.z, v.w);
}

// ---------------------------------------------------------------------------
// LayerNorm -> bf16 hi/lo planes
// ---------------------------------------------------------------------------
__global__ void ln_bf_kernel(const float* __restrict__ x, const float* __restrict__ w,
                             const float* __restrict__ bia,
                             __nv_bfloat16* __restrict__ hi, __nv_bfloat16* __restrict__ lo) {
    __shared__ float red[256];
    const int row = blockIdx.x;
    const int t = threadIdx.x;
    const float* xr = x + (size_t)row * C_;
    float v[3];
    float s = 0.f, s2 = 0.f;
#pragma unroll
    for (int j = 0; j < 3; j++) { v[j] = xr[t + 256 * j]; s += v[j]; s2 += v[j] * v[j]; }
    red[t] = s; __syncthreads();
    for (int o = 128; o > 0; o >>= 1) { if (t < o) red[t] += red[t + o]; __syncthreads(); }
    const float mean = red[0] * (1.f / C_);
    __syncthreads();
    red[t] = s2; __syncthreads();
    for (int o = 128; o > 0; o >>= 1) { if (t < o) red[t] += red[t + o]; __syncthreads(); }
    const float var = red[0] * (1.f / C_) - mean * mean;
    const float rstd = rsqrtf(var + 1e-5f);
#pragma unroll
    for (int j = 0; j < 3; j++) {
        const int c = t + 256 * j;
        const float y = (v[j] - mean) * rstd * w[c] + bia[c];
        const size_t gi = (size_t)row * C_ + c;
        const __nv_bfloat16 h = __float2bfloat16_rn(y);
        hi[gi] = h;
        lo[gi] = __float2bfloat16_rn(y - __bfloat162float(h));
    }
}

// ---------------------------------------------------------------------------
// Flash attention (validated in R6, unchanged)
// ---------------------------------------------------------------------------
__global__ void __launch_bounds__(256) flash_kernel(
    const __nv_bfloat16* __restrict__ QKVhi, const __nv_bfloat16* __restrict__ QKVlo,
    __nv_bfloat16* __restrict__ Ohi, __nv_bfloat16* __restrict__ Olo)
{
    constexpr int LDS = 72;
    constexpr uint32_t QPLANE  = 128 * LDS * 2;
    constexpr uint32_t KVPLANE = 64 * LDS * 2;
    constexpr uint32_t STAGE_B = 4 * KVPLANE;
    extern __shared__ __nv_bfloat16 sm[];
    const uint32_t qbase  = smem_u32(sm);
    const uint32_t kvbase = qbase + 2 * QPLANE;

    const int tid = threadIdx.x;
    const int wid = tid >> 5, lane = tid & 31;
    const int z = blockIdx.y, b = z / H_, hh = z % H_;
    const int row0 = blockIdx.x * 128;

    const __nv_bfloat16* qh = QKVhi + ((size_t)b * N_ + row0) * (3 * C_) + hh * D_;
    const __nv_bfloat16* ql = QKVlo + ((size_t)b * N_ + row0) * (3 * C_) + hh * D_;
    const __nv_bfloat16* kh = QKVhi + (size_t)b * N_ * (3 * C_) + C_ + hh * D_;
    const __nv_bfloat16* kl = QKVlo + (size_t)b * N_ * (3 * C_) + C_ + hh * D_;
    const __nv_bfloat16* vh = QKVhi + (size_t)b * N_ * (3 * C_) + 2 * C_ + hh * D_;
    const __nv_bfloat16* vl = QKVlo + (size_t)b * N_ * (3 * C_) + 2 * C_ + hh * D_;

#pragma unroll
    for (int i = 0; i < 16; i++) {
        const int u = i * 256 + tid;
        const int plane = u >> 11, r = (u >> 4) & 127, seg = u & 15;
        CP_ASYNC8(qbase + plane * QPLANE + (uint32_t)(r * 144 + seg * 8),
                  (plane ? ql : qh) + (size_t)r * (3 * C_) + seg * 4);
    }
    auto issueKV = [&](int c, int stage) {
        const int k0 = c * 64;
#pragma unroll
        for (int i = 0; i < 16; i++) {
            const int u = i * 256 + tid;
            const int plane = u >> 10, r = (u >> 4) & 63, seg = u & 15;
            const __nv_bfloat16* base =
                plane == 0 ? kh : plane == 1 ? kl : plane == 2 ? vh : vl;
            CP_ASYNC8(kvbase + stage * STAGE_B + plane * KVPLANE + (uint32_t)(r * 144 + seg * 8),
                      base + (size_t)(k0 + r) * (3 * C_) + seg * 4);
        }
    };
    issueKV(0, 0);
    CP_COMMIT();

    const int lar = lane & 15, lac = (lane >> 4) * 8;
    const int bq = lane >> 3, br = lane & 7;
    const int brow = (bq >> 1) * 8 + br, bcol = (bq & 1) * 8;

    uint32_t qf[2][4][4];
    float oacc[8][4] = {};
    float m_run0 = -1e30f, m_run1 = -1e30f;
    float l_run0 = 0.f, l_run1 = 0.f;

    for (int c = 0; c < 8; c++) {
        if (c + 1 < 8) issueKV(c + 1, (c + 1) & 1);
        CP_COMMIT();
        CP_WAIT1();
        __syncthreads();
        if (c == 0) {
#pragma unroll
            for (int pl = 0; pl < 2; pl++)
#pragma unroll
                for (int ks = 0; ks < 4; ks++)
                    LDSM_X4(qf[pl][ks][0], qf[pl][ks][1], qf[pl][ks][2], qf[pl][ks][3],
                            qbase + pl * QPLANE +
                            (uint32_t)(((wid * 16 + lar) * LDS + ks * 16 + lac) * 2));
        }
        const uint32_t st = kvbase + (c & 1) * STAGE_B;
        const uint32_t kHi = st, kLo = st + KVPLANE;
        const uint32_t vHi = st + 2 * KVPLANE, vLo = st + 3 * KVPLANE;

        float sacc[8][4] = {};
#pragma unroll
        for (int ks = 0; ks < 4; ks++) {
            uint32_t bh_[8][2], bl_[8][2];
#pragma unroll
            for (int nb = 0; nb < 4; nb++) {
                const uint32_t off = (uint32_t)(((nb * 16 + brow) * LDS + ks * 16 + bcol) * 2);
                LDSM_X4(bh_[2*nb][0], bh_[2*nb][1], bh_[2*nb+1][0], bh_[2*nb+1][1], kHi + off);
                LDSM_X4(bl_[2*nb][0], bl_[2*nb][1], bl_[2*nb+1][0], bl_[2*nb+1][1], kLo + off);
            }
#pragma unroll
            for (int nt = 0; nt < 8; nt++) {
                mma_bf16(sacc[nt], qf[0][ks], bh_[nt]);
                mma_bf16(sacc[nt], qf[0][ks], bl_[nt]);
                mma_bf16(sacc[nt], qf[1][ks], bh_[nt]);
            }
        }

        float mc0 = -1e30f, mc1 = -1e30f;
#pragma unroll
        for (int nt = 0; nt < 8; nt++) {
            mc0 = fmaxf(mc0, fmaxf(sacc[nt][0], sacc[nt][1]));
            mc1 = fmaxf(mc1, fmaxf(sacc[nt][2], sacc[nt][3]));
        }
        mc0 *= 0.125f; mc1 *= 0.125f;
#pragma unroll
        for (int o = 1; o <= 2; o <<= 1) {
            mc0 = fmaxf(mc0, __shfl_xor_sync(0xffffffffu, mc0, o));
            mc1 = fmaxf(mc1, __shfl_xor_sync(0xffffffffu, mc1, o));
        }
        const float mn0 = fmaxf(m_run0, mc0), mn1 = fmaxf(m_run1, mc1);
        const float a0 = __expf(m_run0 - mn0), a1 = __expf(m_run1 - mn1);
        m_run0 = mn0; m_run1 = mn1;
        float lc0 = 0.f, lc1 = 0.f;
#pragma unroll
        for (int nt = 0; nt < 8; nt++) {
            sacc[nt][0] = __expf(sacc[nt][0] * 0.125f - mn0);
            sacc[nt][1] = __expf(sacc[nt][1] * 0.125f - mn0);
            sacc[nt][2] = __expf(sacc[nt][2] * 0.125f - mn1);
            sacc[nt][3] = __expf(sacc[nt][3] * 0.125f - mn1);
            lc0 += sacc[nt][0] + sacc[nt][1];
            lc1 += sacc[nt][2] + sacc[nt][3];
            oacc[nt][0] *= a0; oacc[nt][1] *= a0;
            oacc[nt][2] *= a1; oacc[nt][3] *= a1;
        }
        l_run0 = l_run0 * a0 + lc0;
        l_run1 = l_run1 * a1 + lc1;

#pragma unroll
        for (int ks = 0; ks < 4; ks++) {
            const int t0 = 2 * ks, t1 = t0 + 1;
            uint32_t ph[4], plo_[4];
            split_pair(sacc[t0][0], sacc[t0][1], ph[0], plo_[0]);
            split_pair(sacc[t0][2], sacc[t0][3], ph[1], plo_[1]);
            split_pair(sacc[t1][0], sacc[t1][1], ph[2], plo_[2]);
            split_pair(sacc[t1][2], sacc[t1][3], ph[3], plo_[3]);
            uint32_t vh_[8][2], vl_[8][2];
#pragma unroll
            for (int nb = 0; nb < 4; nb++) {
                const uint32_t off =
                    (uint32_t)(((ks * 16 + (bq & 1) * 8 + br) * LDS + nb * 16 + (bq >> 1) * 8) * 2);
                LDSM_X4_T(vh_[2*nb][0], vh_[2*nb][1], vh_[2*nb+1][0], vh_[2*nb+1][1], vHi + off);
                LDSM_X4_T(vl_[2*nb][0], vl_[2*nb][1], vl_[2*nb+1][0], vl_[2*nb+1][1], vLo + off);
            }
#pragma unroll
            for (int nt = 0; nt < 8; nt++) {
                mma_bf16(oacc[nt], ph, vh_[nt]);
                mma_bf16(oacc[nt], ph, vl_[nt]);
                mma_bf16(oacc[nt], plo_, vh_[nt]);
            }
        }
        __syncthreads();
    }

#pragma unroll
    for (int o = 1; o <= 2; o <<= 1) {
        l_run0 += __shfl_xor_sync(0xffffffffu, l_run0, o);
        l_run1 += __shfl_xor_sync(0xffffffffu, l_run1, o);
    }
    const float inv0 = 1.f / l_run0, inv1 = 1.f / l_run1;
    const int rA = lane >> 2, colb = (lane & 3) * 2;
    const size_t obase = ((size_t)b * N_ + row0 + wid * 16) * C_ + hh * D_;
#pragma unroll
    for (int nt = 0; nt < 8; nt++) {
        split_store(Ohi, Olo, obase + (size_t)rA * C_ + nt * 8 + colb,
                    oacc[nt][0] * inv0, oacc[nt][1] * inv0);
        split_store(Ohi, Olo, obase + (size_t)(rA + 8) * C_ + nt * 8 + colb,
                    oacc[nt][2] * inv1, oacc[nt][3] * inv1);
    }
}

// ---------------------------------------------------------------------------
// bf16-split HMMA GEMM v4: 128-thread CTAs (4 warps), block 128x128,
// warp tile 64x64, BK=32, fragment caching, 2-stage ring, 2 CTAs/SM.
// EPI: 0 -> hi/lo planes; 2 -> 2*(v+bias) fp32; 3 -> gelu(v+bias) planes;
//      4 -> v+bias+res fp32
// ---------------------------------------------------------------------------
template <int EPI>
__global__ void __launch_bounds__(128) mma_gemm4(
    const __nv_bfloat16* __restrict__ Ahi, const __nv_bfloat16* __restrict__ Alo,
    const __nv_bfloat16* __restrict__ Bhi, const __nv_bfloat16* __restrict__ Blo,
    const float* __restrict__ bias, const float* __restrict__ res,
    float* __restrict__ Cf, __nv_bfloat16* __restrict__ Chi, __nv_bfloat16* __restrict__ Clo,
    int K, int lda, int ldb, int ldc)
{
    constexpr int LDS = 40;
    constexpr uint32_t PLANE = 128 * LDS * 2;        // 10240
    constexpr uint32_t STAGE_B = 4 * PLANE;          // 40960
    extern __shared__ __nv_bfloat16 sm[];
    const uint32_t sbase = smem_u32(sm);

    const int tid = threadIdx.x;
    const int wid = tid >> 5, lane = tid & 31;
    const int mOff = (wid & 1) * 64, nOff = (wid >> 1) * 64;

    const int row0 = blockIdx.y * 128, col0 = blockIdx.x * 128;
    const __nv_bfloat16* pl[4] = {
        Ahi + (size_t)row0 * lda, Alo + (size_t)row0 * lda,
        Bhi + (size_t)col0 * ldb, Blo + (size_t)col0 * ldb };

    auto issue = [&](int c, int stage) {
        const int k0 = c * 32;
        const uint32_t sst = sbase + stage * STAGE_B;
        // 4 planes x 128 rows x 4 segs of 16B  (BK=32 bf16 = 64B/row)
#pragma unroll
        for (int i = 0; i < 16; i++) {
            const int u = i * 128 + tid;
            const int plane = u >> 9, r = (u >> 2) & 127, seg = u & 3;
            const int ld = (plane < 2) ? lda : ldb;
            CP_ASYNC16(sst + plane * PLANE + (uint32_t)(r * 80 + seg * 16),
                       pl[plane] + (size_t)r * ld + k0 + seg * 8);
        }
    };

    const int lar = lane & 15, lac = (lane >> 4) * 8;
    const int bq = lane >> 3, br = lane & 7;
    const int brow = (bq >> 1) * 8 + br, bcol = (bq & 1) * 8;

    float acc[4][8][4] = {};

    const int chunks = K / 32;
    issue(0, 0);
    CP_COMMIT();
    for (int c = 0; c < chunks; c++) {
        __syncthreads();   // all warps done computing the stage we're about to overwrite
        if (c + 1 < chunks) issue(c + 1, (c + 1) & 1);
        CP_COMMIT();
        CP_WAIT1();
        __syncthreads();
        const uint32_t sst = sbase + (c & 1) * STAGE_B;
        const uint32_t aHiB = sst, aLoB = sst + PLANE;
        const uint32_t bHiB = sst + 2 * PLANE, bLoB = sst + 3 * PLANE;
#pragma unroll
        for (int kk = 0; kk < 32; kk += 16) {
            uint32_t ah[4][4], bh_[8][2];
#pragma unroll
            for (int mi = 0; mi < 4; mi++)
                LDSM_X4(ah[mi][0], ah[mi][1], ah[mi][2], ah[mi][3],
                        aHiB + (uint32_t)(((mOff + mi * 16 + lar) * LDS + kk + lac) * 2));
#pragma unroll
            for (int nb = 0; nb < 4; nb++)
                LDSM_X4(bh_[2*nb][0], bh_[2*nb][1], bh_[2*nb+1][0], bh_[2*nb+1][1],
                        bHiB + (uint32_t)(((nOff + nb * 16 + brow) * LDS + kk + bcol) * 2));
            // term hh
#pragma unroll
            for (int mi = 0; mi < 4; mi++)
#pragma unroll
                for (int ni = 0; ni < 8; ni++)
                    mma_bf16(acc[mi][ni], ah[mi], bh_[ni]);
            // term hl: aHi x bLo
            {
                uint32_t bl_[8][2];
#pragma unroll
                for (int nb = 0; nb < 4; nb++)
                    LDSM_X4(bl_[2*nb][0], bl_[2*nb][1], bl_[2*nb+1][0], bl_[2*nb+1][1],
                            bLoB + (uint32_t)(((nOff + nb * 16 + brow) * LDS + kk + bcol) * 2));
#pragma unroll
                for (int mi = 0; mi < 4; mi++)
#pragma unroll
                    for (int ni = 0; ni < 8; ni++)
                        mma_bf16(acc[mi][ni], ah[mi], bl_[ni]);
            }
            // term lh: aLo x bHi
            {
                uint32_t al[4][4];
#pragma unroll
                for (int mi = 0; mi < 4; mi++)
                    LDSM_X4(al[mi][0], al[mi][1], al[mi][2], al[mi][3],
                            aLoB + (uint32_t)(((mOff + mi * 16 + lar) * LDS + kk + lac) * 2));
#pragma unroll
                for (int mi = 0; mi < 4; mi++)
#pragma unroll
                    for (int ni = 0; ni < 8; ni++)
                        mma_bf16(acc[mi][ni], al[mi], bh_[ni]);
            }
        }
    }

    // epilogue
#pragma unroll
    for (int mi = 0; mi < 4; mi++) {
#pragma unroll
        for (int ni = 0; ni < 8; ni++) {
#pragma unroll
            for (int h = 0; h < 2; h++) {
                const int r = row0 + mOff + mi * 16 + (lane >> 2) + h * 8;
                const int c = col0 + nOff + ni * 8 + (lane & 3) * 2;
                float v0 = acc[mi][ni][2 * h + 0];
                float v1 = acc[mi][ni][2 * h + 1];
                const size_t gi = (size_t)r * ldc + c;
                if (EPI == 0) {
                    split_store(Chi, Clo, gi, v0, v1);
                } else if (EPI == 2) {
                    *(float2*)(Cf + gi) = make_float2(2.f * (v0 + bias[c]), 2.f * (v1 + bias[c + 1]));
                } else if (EPI == 3) {
                    v0 += bias[c];  v1 += bias[c + 1];
                    v0 = 0.5f * v0 * (1.f + erff(v0 * 0.70710678118654752f));
                    v1 = 0.5f * v1 * (1.f + erff(v1 * 0.70710678118654752f));
                    split_store(Chi, Clo, gi, v0, v1);
                } else {  // EPI 4
                    v0 += bias[c] + res[gi];
                    v1 += bias[c + 1] + res[gi + 1];
                    *(float2*)(Cf + gi) = make_float2(v0, v1);
                }
            }
        }
    }
}

// ---------------------------------------------------------------------------
// Launch sequence
// ---------------------------------------------------------------------------
extern "C" void kernel_launch(void* const* d_in, const int* in_sizes, int n_in,
                              void* d_out, int out_size) {
    (void)in_sizes; (void)n_in; (void)out_size;
    const float* x      = (const float*)d_in[0];
    const float* ln1_w  = (const float*)d_in[1];
    const float* ln1_b  = (const float*)d_in[2];
    const float* qkv_w  = (const float*)d_in[3];
    const float* proj_w = (const float*)d_in[4];
    const float* proj_b = (const float*)d_in[5];
    const float* ln2_w  = (const float*)d_in[6];
    const float* ln2_b  = (const float*)d_in[7];
    const float* fc1_w  = (const float*)d_in[8];
    const float* fc1_b  = (const float*)d_in[9];
    const float* fc2_w  = (const float*)d_in[10];
    const float* fc2_b  = (const float*)d_in[11];
    float* out = (float*)d_out;

    float *xres;
    __nv_bfloat16 *h_hi, *h_lo, *qkv_hi, *qkv_lo, *o_hi, *o_lo, *f1_hi, *f1_lo;
    __nv_bfloat16 *qw_hi, *qw_lo, *pw_hi, *pw_lo, *f1w_hi, *f1w_lo, *f2w_hi, *f2w_lo;
    cudaGetSymbolAddress((void**)&xres,   g_xres);
    cudaGetSymbolAddress((void**)&h_hi,   g_h_hi);   cudaGetSymbolAddress((void**)&h_lo,   g_h_lo);
    cudaGetSymbolAddress((void**)&qkv_hi, g_qkv_hi); cudaGetSymbolAddress((void**)&qkv_lo, g_qkv_lo);
    cudaGetSymbolAddress((void**)&o_hi,   g_o_hi);   cudaGetSymbolAddress((void**)&o_lo,   g_o_lo);
    cudaGetSymbolAddress((void**)&f1_hi,  g_f1_hi);  cudaGetSymbolAddress((void**)&f1_lo,  g_f1_lo);
    cudaGetSymbolAddress((void**)&qw_hi,  g_qkvw_hi);  cudaGetSymbolAddress((void**)&qw_lo,  g_qkvw_lo);
    cudaGetSymbolAddress((void**)&pw_hi,  g_projw_hi); cudaGetSymbolAddress((void**)&pw_lo,  g_projw_lo);
    cudaGetSymbolAddress((void**)&f1w_hi, g_fc1w_hi);  cudaGetSymbolAddress((void**)&f1w_lo, g_fc1w_lo);
    cudaGetSymbolAddress((void**)&f2w_hi, g_fc2w_hi);  cudaGetSymbolAddress((void**)&f2w_lo, g_fc2w_lo);

    constexpr int SMEM_GEMM  = 2 * 4 * 128 * 40 * 2;                     // 81920
    constexpr int SMEM_FLASH = 2 * 128 * 72 * 2 + 2 * 4 * 64 * 72 * 2;   // 110592
    cudaFuncSetAttribute(mma_gemm4<0>, cudaFuncAttributeMaxDynamicSharedMemorySize, SMEM_GEMM);
    cudaFuncSetAttribute(mma_gemm4<2>, cudaFuncAttributeMaxDynamicSharedMemorySize, SMEM_GEMM);
    cudaFuncSetAttribute(mma_gemm4<3>, cudaFuncAttributeMaxDynamicSharedMemorySize, SMEM_GEMM);
    cudaFuncSetAttribute(mma_gemm4<4>, cudaFuncAttributeMaxDynamicSharedMemorySize, SMEM_GEMM);
    cudaFuncSetAttribute(flash_kernel, cudaFuncAttributeMaxDynamicSharedMemorySize, SMEM_FLASH);

    // 0. pre-split weights to bf16 hi/lo
    cvt_kernel<<<(3 * C_ * C_ / 4 + 255) / 256, 256>>>(qkv_w,  qw_hi,  qw_lo,  3 * C_ * C_ / 4);
    cvt_kernel<<<(C_ * C_ / 4 + 255) / 256, 256>>>(proj_w, pw_hi,  pw_lo,  C_ * C_ / 4);
    cvt_kernel<<<(HID_ * C_ / 4 + 255) / 256, 256>>>(fc1_w,  f1w_hi, f1w_lo, HID_ * C_ / 4);
    cvt_kernel<<<(C_ * HID_ / 4 + 255) / 256, 256>>>(fc2_w,  f2w_hi, f2w_lo, C_ * HID_ / 4);

    // 1. LN1 -> h planes
    ln_bf_kernel<<<M_, 256>>>(x, ln1_w, ln1_b, h_hi, h_lo);
    // 2. QKV -> qkv planes
    mma_gemm4<0><<<dim3(18, 128, 1), 128, SMEM_GEMM>>>(
        h_hi, h_lo, qw_hi, qw_lo, nullptr, nullptr, nullptr, qkv_hi, qkv_lo,
        C_, C_, C_, 3 * C_);
    // 3-5. flash attention -> o planes
    flash_kernel<<<dim3(4, BH_), 256, SMEM_FLASH>>>(qkv_hi, qkv_lo, o_hi, o_lo);
    // 6. xres = 2*(o @ proj_w^T + proj_b)
    mma_gemm4<2><<<dim3(6, 128, 1), 128, SMEM_GEMM>>>(
        o_hi, o_lo, pw_hi, pw_lo, proj_b, nullptr, xres, nullptr, nullptr,
        C_, C_, C_, C_);
    // 7. LN2 -> h planes
    ln_bf_kernel<<<M_, 256>>>(xres, ln2_w, ln2_b, h_hi, h_lo);
    // 8. fc1 + GELU -> f1 planes
    mma_gemm4<3><<<dim3(24, 128, 1), 128, SMEM_GEMM>>>(
        h_hi, h_lo, f1w_hi, f1w_lo, fc1_b, nullptr, nullptr, f1_hi, f1_lo,
        C_, C_, C_, HID_);
    // 9. out = xres + f1 @ fc2_w^T + fc2_b   (grid fix: 6 column tiles, was 3)
    mma_gemm4<4><<<dim3(6, 128, 1), 128, SMEM_GEMM>>>(
        f1_hi, f1_lo, f2w_hi, f2w_lo, fc2_b, xres, out, nullptr, nullptr,
        HID_, HID_, HID_, C_);
}